// round 10
// baseline (speedup 1.0000x reference)
#include <cuda_runtime.h>
#include <math.h>
#include <stdint.h>

#define C_IN   256
#define HGT    200
#define WID    200
#define HWNUM  40000
#define NA     9
#define KTOT   2304
#define NSCORE 360000
#define PRE    6000
#define POST   1000
#define IMGSZ  1600.0f
#define NMS_THR 0.7f
#define MINSZ  1.0f
#define BCLIP  4.135166556742356f   /* log(1000/16) */
#define MASKW  94                   /* ceil(6000/64) */

/* ------------------------- scratch (device globals) ------------------------ */
__device__ float              g_wT[KTOT * 256];           /* w transposed: [k'][m] */
__device__ float              g_t[C_IN * HWNUM];          /* conv output (relu'd) */
__device__ unsigned int       g_keys[NSCORE];             /* monotone score keys  */
__device__ float              g_deltas[NSCORE * 4];
__device__ int                g_hist1[65536];
__device__ int                g_hist2[65536];
__device__ int                g_selHigh;
__device__ int                g_cntAbove1;
__device__ unsigned int       g_T;
__device__ int                g_nAbove;
__device__ int                g_cntHigh;
__device__ int                g_cntEq;
__device__ unsigned int       g_tieIdx[8192];
__device__ unsigned long long g_list[8192];               /* (key<<32)|(~idx)     */
__device__ float              g_boxes[PRE * 4];
__device__ int                g_valid[PRE];
__device__ unsigned long long g_mask[(size_t)PRE * MASKW];

/* --------------------------------- zero ----------------------------------- */
__global__ void zero_kernel() {
    int i = blockIdx.x * blockDim.x + threadIdx.x;
    if (i < 65536) { g_hist1[i] = 0; g_hist2[i] = 0; }
    if (i == 0) { g_cntHigh = 0; g_cntEq = 0; }
}

/* ------------- one-time weight transpose: wT[k'][m], k'=(rs,ci) ------------ */
__global__ void transpose_w_kernel(const float* __restrict__ w) {
    int idx = blockIdx.x * blockDim.x + threadIdx.x;   /* write-coalesced in m */
    if (idx >= KTOT * 256) return;
    int kp = idx >> 8;          /* k' = rs*256 + ci */
    int m  = idx & 255;
    int ci = kp & 255;
    int rs = kp >> 8;
    g_wT[idx] = w[(size_t)m * KTOT + ci * 9 + rs];
}

/* ---- 3x3 conv (implicit GEMM, sequential FMA over k' = (r,s,ci) order) ---- */
/* Bit-exact anchor: one accumulator per output, k' stepped 0..2303 ascending. */
/* Tile 64(m) x 128(p), thread tile 4x8 -> 1252 blocks for load balance.       */
__global__ __launch_bounds__(256, 3)
void conv3x3_kernel(const float* __restrict__ x, const float* __restrict__ bias) {
    __shared__ __align__(16) float As[2][8][64];
    __shared__ __align__(16) float Bs[2][8][128];
    const int tid = threadIdx.x;
    const int m0 = blockIdx.y * 64;
    const int p0 = blockIdx.x * 128;
    const int a_kr = tid >> 4;          /* 0..7 for tid<128  */
    const int a_mc = (tid & 15) * 4;    /* 0..60             */
    const int b_kr = tid >> 5;          /* 0..7              */
    const int b_pc = (tid & 31) * 4;    /* 0..124            */
    const int tx = tid & 15, ty = tid >> 4;

    float4 aReg = make_float4(0.f, 0.f, 0.f, 0.f);
    float4 bReg = make_float4(0.f, 0.f, 0.f, 0.f);

    auto loadTiles = [&](int it) {
        int k0 = it * 8;
        if (tid < 128)
            aReg = *reinterpret_cast<const float4*>(
                &g_wT[(size_t)(k0 + a_kr) * 256 + m0 + a_mc]);
        int kp = k0 + b_kr;
        int rs = kp >> 8;
        int ci = kp & 255;
        int r = rs / 3 - 1;
        int s = rs - (rs / 3) * 3 - 1;
        const float* base = x + (size_t)ci * HWNUM;
        float bv[4];
#pragma unroll
        for (int jj = 0; jj < 4; jj++) {
            int p = p0 + b_pc + jj;
            float v = 0.f;
            if (p < HWNUM) {
                int h = p / 200;
                int wc = p - h * 200;
                int hh = h + r, wcc = wc + s;
                if (hh >= 0 && hh < HGT && wcc >= 0 && wcc < WID)
                    v = base[hh * WID + wcc];
            }
            bv[jj] = v;
        }
        bReg = make_float4(bv[0], bv[1], bv[2], bv[3]);
    };
    auto storeTiles = [&](int buf) {
        if (tid < 128)
            *reinterpret_cast<float4*>(&As[buf][a_kr][a_mc]) = aReg;
        *reinterpret_cast<float4*>(&Bs[buf][b_kr][b_pc]) = bReg;
    };

    float acc[4][8];
#pragma unroll
    for (int i = 0; i < 4; i++)
#pragma unroll
        for (int j = 0; j < 8; j++) acc[i][j] = 0.f;

    loadTiles(0);
    storeTiles(0);
    __syncthreads();
    int cur = 0;
    const int NIT = KTOT / 8;  /* 288 */
    for (int it = 0; it < NIT; it++) {
        if (it + 1 < NIT) loadTiles(it + 1);
#pragma unroll
        for (int kk = 0; kk < 8; kk++) {
            float4 a0 = *reinterpret_cast<const float4*>(&As[cur][kk][ty * 4]);
            float4 b0 = *reinterpret_cast<const float4*>(&Bs[cur][kk][tx * 4]);
            float4 b1 = *reinterpret_cast<const float4*>(&Bs[cur][kk][64 + tx * 4]);
            float av[4] = {a0.x, a0.y, a0.z, a0.w};
            float bv[8] = {b0.x, b0.y, b0.z, b0.w, b1.x, b1.y, b1.z, b1.w};
#pragma unroll
            for (int i = 0; i < 4; i++)
#pragma unroll
                for (int j = 0; j < 8; j++)
                    acc[i][j] = fmaf(av[i], bv[j], acc[i][j]);
        }
        if (it + 1 < NIT) {
            storeTiles(cur ^ 1);
            __syncthreads();
            cur ^= 1;
        }
    }
    /* epilogue: columns p0+tx*4 (j 0-3) and p0+64+tx*4 (j 4-7) */
#pragma unroll
    for (int i = 0; i < 4; i++) {
        int m = m0 + ty * 4 + i;
        float bv = bias[m];
        float4 o0, o1;
        o0.x = fmaxf(__fadd_rn(acc[i][0], bv), 0.f);
        o0.y = fmaxf(__fadd_rn(acc[i][1], bv), 0.f);
        o0.z = fmaxf(__fadd_rn(acc[i][2], bv), 0.f);
        o0.w = fmaxf(__fadd_rn(acc[i][3], bv), 0.f);
        o1.x = fmaxf(__fadd_rn(acc[i][4], bv), 0.f);
        o1.y = fmaxf(__fadd_rn(acc[i][5], bv), 0.f);
        o1.z = fmaxf(__fadd_rn(acc[i][6], bv), 0.f);
        o1.w = fmaxf(__fadd_rn(acc[i][7], bv), 0.f);
        int pA = p0 + tx * 4;
        int pB = p0 + 64 + tx * 4;
        if (pA < HWNUM) *reinterpret_cast<float4*>(&g_t[(size_t)m * HWNUM + pA]) = o0;
        if (pB < HWNUM) *reinterpret_cast<float4*>(&g_t[(size_t)m * HWNUM + pB]) = o1;
    }
}

/* --- 1x1 heads (plain sequential FMA) + fused hist1; 128 thr, 313 blocks --- */
__global__ __launch_bounds__(128)
void heads_kernel(const float* __restrict__ wObj, const float* __restrict__ bObj,
                  const float* __restrict__ wReg, const float* __restrict__ bReg) {
    __shared__ float ws[45 * 256];
    __shared__ float bs[45];
    int tid = threadIdx.x;
    for (int i = tid; i < 9 * 256; i += 128) ws[i] = wObj[i];
    for (int i = tid; i < 36 * 256; i += 128) ws[9 * 256 + i] = wReg[i];
    if (tid < 9) bs[tid] = bObj[tid];
    if (tid < 36) bs[9 + tid] = bReg[tid];
    __syncthreads();

    int p = blockIdx.x * 128 + tid;
    if (p >= HWNUM) return;
    float acc[45];
#pragma unroll
    for (int o = 0; o < 45; o++) acc[o] = 0.f;
#pragma unroll 4
    for (int ci = 0; ci < 256; ci++) {
        float a = g_t[(size_t)ci * HWNUM + p];
#pragma unroll
        for (int o = 0; o < 45; o++)
            acc[o] = fmaf(a, ws[o * 256 + ci], acc[o]);
    }
#pragma unroll
    for (int a = 0; a < 9; a++) {
        float s = __fadd_rn(acc[a], bs[a]);
        unsigned u = __float_as_uint(s);
        unsigned key = (u & 0x80000000u) ? ~u : (u | 0x80000000u);
        g_keys[p * 9 + a] = key;
        atomicAdd(&g_hist1[key >> 16], 1);
    }
#pragma unroll
    for (int c = 0; c < 36; c++)
        g_deltas[(size_t)p * 36 + c] = __fadd_rn(acc[9 + c], bs[9 + c]);
}

/* ------------------------------ radix select ------------------------------- */
__global__ void select_kernel(int pass) {
    const int* hist = (pass == 0) ? g_hist1 : g_hist2;
    __shared__ int csum[1024];
    __shared__ int sbase;
    int t = threadIdx.x;
    if (t == 0) sbase = (pass == 0) ? 0 : g_cntAbove1;
    __syncthreads();
    int base = sbase;
    int s = 0;
    int start = t * 64;
    for (int k = 0; k < 64; k++) s += hist[65535 - (start + k)];
    csum[t] = s;
    __syncthreads();
    for (int off = 1; off < 1024; off <<= 1) {
        int v = (t >= off) ? csum[t - off] : 0;
        __syncthreads();
        csum[t] += v;
        __syncthreads();
    }
    int incl = csum[t];
    int excl = incl - s;
    if (base + excl < PRE && base + incl >= PRE) {
        int acc = base + excl;
        for (int k = 0; k < 64; k++) {
            int b = 65535 - (start + k);
            int c = hist[b];
            if (acc + c >= PRE) {
                if (pass == 0) { g_selHigh = b; g_cntAbove1 = acc; }
                else { g_T = (((unsigned)g_selHigh) << 16) | (unsigned)b; g_nAbove = acc; }
                break;
            }
            acc += c;
        }
    }
}

__global__ void hist2_kernel() {
    int i = blockIdx.x * blockDim.x + threadIdx.x;
    if (i < NSCORE) {
        unsigned k = g_keys[i];
        if ((int)(k >> 16) == g_selHigh) atomicAdd(&g_hist2[k & 0xFFFFu], 1);
    }
}

__global__ void compact_kernel() {
    int i = blockIdx.x * blockDim.x + threadIdx.x;
    if (i >= NSCORE) return;
    unsigned k = g_keys[i];
    unsigned T = g_T;
    if (k > T) {
        int pos = atomicAdd(&g_cntHigh, 1);
        g_list[pos] = (((unsigned long long)k) << 32) |
                      (unsigned long long)(0xFFFFFFFFu - (unsigned)i);
    } else if (k == T) {
        int pos = atomicAdd(&g_cntEq, 1);
        if (pos < 8192) g_tieIdx[pos] = (unsigned)i;
    }
}

/* sort tie indices ascending (bitonic bounded by next-pow2), append, pad */
__global__ void finalize_kernel() {
    __shared__ unsigned sIdx[8192];
    int t = threadIdx.x;
    int cnt = g_cntEq; if (cnt > 8192) cnt = 8192;
    int need = PRE - g_nAbove;
    int n2 = 32;
    while (n2 < cnt) n2 <<= 1;
    for (int i = t; i < n2; i += 1024) sIdx[i] = (i < cnt) ? g_tieIdx[i] : 0xFFFFFFFFu;
    __syncthreads();
    for (int k = 2; k <= n2; k <<= 1)
        for (int j = k >> 1; j > 0; j >>= 1) {
            for (int i = t; i < n2; i += 1024) {
                int l = i ^ j;
                if (l > i) {
                    unsigned a = sIdx[i], b = sIdx[l];
                    bool up = ((i & k) == 0);
                    if ((a > b) == up) { sIdx[i] = b; sIdx[l] = a; }
                }
            }
            __syncthreads();
        }
    unsigned T = g_T;
    int nA = g_nAbove;
    for (int j = t; j < need; j += 1024)
        g_list[nA + j] = (((unsigned long long)T) << 32) |
                         (unsigned long long)(0xFFFFFFFFu - sIdx[j]);
    for (int j = PRE + t; j < 8192; j += 1024) g_list[j] = 0ull;
}

/* descending bitonic sort of the 8192 composites (zeros sink to the end) */
__global__ void sort_kernel() {
    extern __shared__ unsigned long long sm[];
    int t = threadIdx.x;
    for (int i = t; i < 8192; i += 1024) sm[i] = g_list[i];
    __syncthreads();
    for (int k = 2; k <= 8192; k <<= 1)
        for (int j = k >> 1; j > 0; j >>= 1) {
            for (int i = t; i < 8192; i += 1024) {
                int l = i ^ j;
                if (l > i) {
                    unsigned long long a = sm[i], b = sm[l];
                    bool up = ((i & k) == 0);
                    if ((a < b) == up) { sm[i] = b; sm[l] = a; }
                }
            }
            __syncthreads();
        }
    for (int i = t; i < 8192; i += 1024) g_list[i] = sm[i];
}

/* ---------------- decode/clip — exact fp32, UNFUSED (match XLA) ------------ */
__global__ void decode_kernel(const float* __restrict__ anchors) {
    int j = blockIdx.x * blockDim.x + threadIdx.x;
    if (j >= PRE) return;
    unsigned long long comp = g_list[j];
    unsigned idx = 0xFFFFFFFFu - (unsigned)(comp & 0xFFFFFFFFull);
    float4 an = reinterpret_cast<const float4*>(anchors)[idx];
    float4 dl = reinterpret_cast<const float4*>(g_deltas)[idx];
    float wa = __fsub_rn(an.z, an.x);
    float ha = __fsub_rn(an.w, an.y);
    float xa = __fadd_rn(an.x, __fmul_rn(0.5f, wa));
    float ya = __fadd_rn(an.y, __fmul_rn(0.5f, ha));
    float dw = fminf(dl.z, BCLIP), dh = fminf(dl.w, BCLIP);
    float cx = __fadd_rn(__fmul_rn(dl.x, wa), xa);
    float cy = __fadd_rn(__fmul_rn(dl.y, ha), ya);
    float ew = (float)exp((double)dw);   /* exactly-rounded fp32 exp */
    float eh = (float)exp((double)dh);
    float wb = __fmul_rn(ew, wa);
    float hb = __fmul_rn(eh, ha);
    float x1 = __fsub_rn(cx, __fmul_rn(0.5f, wb));
    float y1 = __fsub_rn(cy, __fmul_rn(0.5f, hb));
    float x2 = __fadd_rn(cx, __fmul_rn(0.5f, wb));
    float y2 = __fadd_rn(cy, __fmul_rn(0.5f, hb));
    x1 = fminf(fmaxf(x1, 0.f), IMGSZ);
    y1 = fminf(fmaxf(y1, 0.f), IMGSZ);
    x2 = fminf(fmaxf(x2, 0.f), IMGSZ);
    y2 = fminf(fmaxf(y2, 0.f), IMGSZ);
    reinterpret_cast<float4*>(g_boxes)[j] = make_float4(x1, y1, x2, y2);
    g_valid[j] = (__fsub_rn(x2, x1) >= MINSZ) && (__fsub_rn(y2, y1) >= MINSZ);
}

/* ----------- NMS suppression mask — exact fp32, UNFUSED (match XLA) -------- */
__global__ void nms_mask_kernel() {
    int rb = blockIdx.y, cb = blockIdx.x;
    if (cb < rb) return;
    int t = threadIdx.x;
    __shared__ float4 cbox[64];
    int j0 = cb * 64;
    int jg = j0 + t;
    cbox[t] = (jg < PRE) ? reinterpret_cast<const float4*>(g_boxes)[jg]
                         : make_float4(0.f, 0.f, 0.f, 0.f);
    __syncthreads();
    int i = rb * 64 + t;
    if (i >= PRE) return;
    unsigned long long bits = 0ull;
    if (j0 + 63 > i) {
        float4 b = reinterpret_cast<const float4*>(g_boxes)[i];
        float a1 = __fmul_rn(__fsub_rn(b.z, b.x), __fsub_rn(b.w, b.y));
        int jmax = min(64, PRE - j0);
        for (int jj = 0; jj < jmax; jj++) {
            int j = j0 + jj;
            if (j <= i) continue;
            float4 c = cbox[jj];
            float lx = fmaxf(b.x, c.x), ly = fmaxf(b.y, c.y);
            float rx = fminf(b.z, c.z), ry = fminf(b.w, c.w);
            float iw = fmaxf(__fsub_rn(rx, lx), 0.f);
            float ih = fmaxf(__fsub_rn(ry, ly), 0.f);
            float inter = __fmul_rn(iw, ih);
            float a2 = __fmul_rn(__fsub_rn(c.z, c.x), __fsub_rn(c.w, c.y));
            float den = fmaxf(__fsub_rn(__fadd_rn(a1, a2), inter), 1e-6f);
            float iou = __fdiv_rn(inter, den);
            if (iou > NMS_THR) bits |= (1ull << jj);
        }
    }
    g_mask[(size_t)i * MASKW + cb] = bits;
}

/* ------ greedy scan: chunked smem prefetch (256 thr) + warp-0 serial ------- */
#define CHUNK 64
__global__ void nms_scan_kernel(float* __restrict__ out) {
    extern __shared__ unsigned long long sm2[];
    unsigned long long (*rows)[MASKW] =
        reinterpret_cast<unsigned long long (*)[MASKW]>(sm2);
    volatile unsigned long long* rem = sm2 + CHUNK * MASKW;  /* 94 words */
    __shared__ int s_nkept;
    int tid = threadIdx.x;
    for (int i = tid; i < POST * 4; i += 256) out[i] = 0.f;
    for (int w = tid; w < MASKW; w += 256) {
        unsigned long long m = 0ull;
        int base = w * 64;
        for (int k = 0; k < 64; k++) {
            int j = base + k;
            if (j >= PRE || !g_valid[j]) m |= (1ull << k);
        }
        rem[w] = m;
    }
    if (tid == 0) s_nkept = 0;
    __syncthreads();

    for (int c = 0; c < MASKW; c++) {
        int base_i = c * CHUNK;
        for (int idx = tid; idx < CHUNK * MASKW; idx += 256) {
            int rr = idx / MASKW, col = idx - rr * MASKW;
            int gi = base_i + rr;
            rows[rr][col] = (gi < PRE && col >= c) ? g_mask[(size_t)gi * MASKW + col] : 0ull;
        }
        __syncthreads();
        if (tid < 32) {
            int lane = tid;
            int nk = s_nkept;
            for (int bit = 0; bit < CHUNK; bit++) {
                int i = base_i + bit;
                if (i >= PRE || nk >= POST) break;
                if (!((rem[c] >> bit) & 1ull)) {
                    if (lane < 4) out[nk * 4 + lane] = g_boxes[i * 4 + lane];
                    nk++;
                    for (int w = c + lane; w < MASKW; w += 32)
                        rem[w] = rem[w] | rows[bit][w];
                    __syncwarp();
                }
            }
            if (lane == 0) s_nkept = nk;
        }
        __syncthreads();
        if (s_nkept >= POST) break;
        __syncthreads();
    }
}

/* --------------------------------- launch ---------------------------------- */
extern "C" void kernel_launch(void* const* d_in, const int* in_sizes, int n_in,
                              void* d_out, int out_size) {
    (void)in_sizes; (void)n_in; (void)out_size;
    const float* feature = (const float*)d_in[0];
    const float* anchors = (const float*)d_in[1];
    const float* w_conv  = (const float*)d_in[2];
    const float* b_conv  = (const float*)d_in[3];
    const float* w_obj   = (const float*)d_in[4];
    const float* b_obj   = (const float*)d_in[5];
    const float* w_reg   = (const float*)d_in[6];
    const float* b_reg   = (const float*)d_in[7];
    float* out = (float*)d_out;

    cudaFuncSetAttribute(sort_kernel, cudaFuncAttributeMaxDynamicSharedMemorySize, 65536);
    cudaFuncSetAttribute(nms_scan_kernel, cudaFuncAttributeMaxDynamicSharedMemorySize, 65536);

    zero_kernel<<<256, 256>>>();
    transpose_w_kernel<<<(KTOT * 256 + 255) / 256, 256>>>(w_conv);
    conv3x3_kernel<<<dim3(313, 4), 256>>>(feature, b_conv);
    heads_kernel<<<313, 128>>>(w_obj, b_obj, w_reg, b_reg);
    select_kernel<<<1, 1024>>>(0);
    hist2_kernel<<<1407, 256>>>();
    select_kernel<<<1, 1024>>>(1);
    compact_kernel<<<1407, 256>>>();
    finalize_kernel<<<1, 1024>>>();
    sort_kernel<<<1, 1024, 65536>>>();
    decode_kernel<<<24, 256>>>(anchors);
    nms_mask_kernel<<<dim3(94, 94), 64>>>();
    nms_scan_kernel<<<1, 256, (CHUNK * MASKW + MASKW) * 8>>>(out);
}

// round 12
// speedup vs baseline: 1.0530x; 1.0530x over previous
#include <cuda_runtime.h>
#include <math.h>
#include <stdint.h>

#define C_IN   256
#define HGT    200
#define WID    200
#define HWNUM  40000
#define NA     9
#define KTOT   2304
#define NSCORE 360000
#define PRE    6000
#define POST   1000
#define IMGSZ  1600.0f
#define NMS_THR 0.7f
#define MINSZ  1.0f
#define BCLIP  4.135166556742356f   /* log(1000/16) */
#define MASKW  94                   /* ceil(6000/64) */

/* ------------------------- scratch (device globals) ------------------------ */
__device__ float              g_wT[KTOT * 256];           /* w transposed: [k'][m] */
__device__ float              g_t[C_IN * HWNUM];          /* conv output (relu'd) */
__device__ unsigned int       g_keys[NSCORE];             /* monotone score keys  */
__device__ float              g_deltas[NSCORE * 4];
__device__ int                g_hist1[65536];
__device__ int                g_hist2[65536];
__device__ int                g_selHigh;
__device__ int                g_cntAbove1;
__device__ unsigned int       g_T;
__device__ int                g_nAbove;
__device__ int                g_cntHigh;
__device__ int                g_cntEq;
__device__ unsigned int       g_tieIdx[8192];
__device__ unsigned long long g_list[8192];               /* (key<<32)|(~idx)     */
__device__ float              g_boxes[PRE * 4];
__device__ int                g_valid[PRE];
__device__ unsigned long long g_mask[(size_t)PRE * MASKW];

/* ------- fused: zero hists/counters + weight transpose wT[k'][m] ----------- */
__global__ void prep_kernel(const float* __restrict__ w) {
    int idx = blockIdx.x * blockDim.x + threadIdx.x;
    if (idx < 65536) { g_hist1[idx] = 0; g_hist2[idx] = 0; }
    if (idx == 0) { g_cntHigh = 0; g_cntEq = 0; }
    if (idx < KTOT * 256) {
        int kp = idx >> 8;          /* k' = rs*256 + ci */
        int m  = idx & 255;
        int ci = kp & 255;
        int rs = kp >> 8;
        g_wT[idx] = w[(size_t)m * KTOT + ci * 9 + rs];
    }
}

/* ---- 3x3 conv (implicit GEMM, sequential FMA over k' = (r,s,ci) order) ---- */
/* Bit-exact anchor: one accumulator per output, k' stepped 0..2303 ascending. */
/* Proven-best config: 128x128 tile, 8x8 thread tile, conflict-free B split.   */
__global__ __launch_bounds__(256, 2)
void conv3x3_kernel(const float* __restrict__ x, const float* __restrict__ bias) {
    __shared__ __align__(16) float As[2][8][128];
    __shared__ __align__(16) float Bs[2][8][128];
    const int tid = threadIdx.x;
    const int m0 = blockIdx.y * 128;
    const int p0 = blockIdx.x * 128;
    const int kr = tid >> 5;           /* 0..7   : k-row within tile   */
    const int lc = (tid & 31) * 4;     /* 0..124 : column (m or p)     */
    const int tx = tid & 15, ty = tid >> 4;

    float4 aReg = make_float4(0.f, 0.f, 0.f, 0.f);
    float4 bReg = make_float4(0.f, 0.f, 0.f, 0.f);

    auto loadTiles = [&](int it) {
        int k0 = it * 8;
        aReg = *reinterpret_cast<const float4*>(&g_wT[(size_t)(k0 + kr) * 256 + m0 + lc]);
        int kp = k0 + kr;
        int rs = kp >> 8;
        int ci = kp & 255;
        int r = rs / 3 - 1;
        int s = rs - (rs / 3) * 3 - 1;
        const float* base = x + (size_t)ci * HWNUM;
        float bv[4];
#pragma unroll
        for (int jj = 0; jj < 4; jj++) {
            int p = p0 + lc + jj;
            float v = 0.f;
            if (p < HWNUM) {
                int h = p / 200;
                int wc = p - h * 200;
                int hh = h + r, wcc = wc + s;
                if (hh >= 0 && hh < HGT && wcc >= 0 && wcc < WID)
                    v = base[hh * WID + wcc];
            }
            bv[jj] = v;
        }
        bReg = make_float4(bv[0], bv[1], bv[2], bv[3]);
    };
    auto storeTiles = [&](int buf) {
        *reinterpret_cast<float4*>(&As[buf][kr][lc]) = aReg;
        *reinterpret_cast<float4*>(&Bs[buf][kr][lc]) = bReg;
    };

    float acc[8][8];
#pragma unroll
    for (int i = 0; i < 8; i++)
#pragma unroll
        for (int j = 0; j < 8; j++) acc[i][j] = 0.f;

    loadTiles(0);
    storeTiles(0);
    __syncthreads();
    int cur = 0;
    const int NIT = KTOT / 8;  /* 288 */
    for (int it = 0; it < NIT; it++) {
        if (it + 1 < NIT) loadTiles(it + 1);
#pragma unroll
        for (int kk = 0; kk < 8; kk++) {
            float4 a0 = *reinterpret_cast<const float4*>(&As[cur][kk][ty * 8]);
            float4 a1 = *reinterpret_cast<const float4*>(&As[cur][kk][ty * 8 + 4]);
            float4 b0 = *reinterpret_cast<const float4*>(&Bs[cur][kk][tx * 4]);
            float4 b1 = *reinterpret_cast<const float4*>(&Bs[cur][kk][64 + tx * 4]);
            float av[8] = {a0.x, a0.y, a0.z, a0.w, a1.x, a1.y, a1.z, a1.w};
            float bv[8] = {b0.x, b0.y, b0.z, b0.w, b1.x, b1.y, b1.z, b1.w};
#pragma unroll
            for (int i = 0; i < 8; i++)
#pragma unroll
                for (int j = 0; j < 8; j++)
                    acc[i][j] = fmaf(av[i], bv[j], acc[i][j]);
        }
        if (it + 1 < NIT) {
            storeTiles(cur ^ 1);
            __syncthreads();
            cur ^= 1;
        }
    }
    /* epilogue: columns p0+tx*4 (j 0-3) and p0+64+tx*4 (j 4-7) */
#pragma unroll
    for (int i = 0; i < 8; i++) {
        int m = m0 + ty * 8 + i;
        float bv = bias[m];
        float4 o0, o1;
        o0.x = fmaxf(__fadd_rn(acc[i][0], bv), 0.f);
        o0.y = fmaxf(__fadd_rn(acc[i][1], bv), 0.f);
        o0.z = fmaxf(__fadd_rn(acc[i][2], bv), 0.f);
        o0.w = fmaxf(__fadd_rn(acc[i][3], bv), 0.f);
        o1.x = fmaxf(__fadd_rn(acc[i][4], bv), 0.f);
        o1.y = fmaxf(__fadd_rn(acc[i][5], bv), 0.f);
        o1.z = fmaxf(__fadd_rn(acc[i][6], bv), 0.f);
        o1.w = fmaxf(__fadd_rn(acc[i][7], bv), 0.f);
        int pA = p0 + tx * 4;
        int pB = p0 + 64 + tx * 4;
        if (pA < HWNUM) *reinterpret_cast<float4*>(&g_t[(size_t)m * HWNUM + pA]) = o0;
        if (pB < HWNUM) *reinterpret_cast<float4*>(&g_t[(size_t)m * HWNUM + pB]) = o1;
    }
}

/* --- 1x1 heads: 3 threads/pixel x 15 outputs each (occupancy fix) ---------- */
/* Each output channel still accumulates sequentially over ci in ONE thread    */
/* -> bit-exact. 625 blocks x 192 threads = 3750 warps chip-wide.              */
__global__ __launch_bounds__(192)
void heads_kernel(const float* __restrict__ wObj, const float* __restrict__ bObj,
                  const float* __restrict__ wReg, const float* __restrict__ bReg) {
    __shared__ float ws[45 * 256];
    __shared__ float bs[45];
    int tid = threadIdx.x;
    for (int i = tid; i < 9 * 256; i += 192) ws[i] = wObj[i];
    for (int i = tid; i < 36 * 256; i += 192) ws[9 * 256 + i] = wReg[i];
    if (tid < 9) bs[tid] = bObj[tid];
    if (tid < 36) bs[9 + tid] = bReg[tid];
    __syncthreads();

    int og = tid / 64;                 /* 0..2  : output group (15 ch each) */
    int px = tid - og * 64;            /* 0..63 : pixel within block        */
    int p = blockIdx.x * 64 + px;
    if (p >= HWNUM) return;
    const float* wsg = ws + og * 15 * 256;
    float acc[15];
#pragma unroll
    for (int o = 0; o < 15; o++) acc[o] = 0.f;
#pragma unroll 4
    for (int ci = 0; ci < 256; ci++) {
        float a = g_t[(size_t)ci * HWNUM + p];
#pragma unroll
        for (int o = 0; o < 15; o++)
            acc[o] = fmaf(a, wsg[o * 256 + ci], acc[o]);
    }
#pragma unroll
    for (int oo = 0; oo < 15; oo++) {
        int o = og * 15 + oo;
        float s = __fadd_rn(acc[oo], bs[o]);
        if (o < 9) {
            unsigned u = __float_as_uint(s);
            unsigned key = (u & 0x80000000u) ? ~u : (u | 0x80000000u);
            g_keys[p * 9 + o] = key;
            atomicAdd(&g_hist1[key >> 16], 1);
        } else {
            g_deltas[(size_t)p * 36 + (o - 9)] = s;
        }
    }
}

/* ------------------------------ radix select ------------------------------- */
__global__ void select_kernel(int pass) {
    const int* hist = (pass == 0) ? g_hist1 : g_hist2;
    __shared__ int csum[1024];
    __shared__ int sbase;
    int t = threadIdx.x;
    if (t == 0) sbase = (pass == 0) ? 0 : g_cntAbove1;
    __syncthreads();
    int base = sbase;
    int s = 0;
    int start = t * 64;
    for (int k = 0; k < 64; k++) s += hist[65535 - (start + k)];
    csum[t] = s;
    __syncthreads();
    for (int off = 1; off < 1024; off <<= 1) {
        int v = (t >= off) ? csum[t - off] : 0;
        __syncthreads();
        csum[t] += v;
        __syncthreads();
    }
    int incl = csum[t];
    int excl = incl - s;
    if (base + excl < PRE && base + incl >= PRE) {
        int acc = base + excl;
        for (int k = 0; k < 64; k++) {
            int b = 65535 - (start + k);
            int c = hist[b];
            if (acc + c >= PRE) {
                if (pass == 0) { g_selHigh = b; g_cntAbove1 = acc; }
                else { g_T = (((unsigned)g_selHigh) << 16) | (unsigned)b; g_nAbove = acc; }
                break;
            }
            acc += c;
        }
    }
}

__global__ void hist2_kernel() {
    int i = blockIdx.x * blockDim.x + threadIdx.x;
    if (i < NSCORE) {
        unsigned k = g_keys[i];
        if ((int)(k >> 16) == g_selHigh) atomicAdd(&g_hist2[k & 0xFFFFu], 1);
    }
}

__global__ void compact_kernel() {
    int i = blockIdx.x * blockDim.x + threadIdx.x;
    if (i >= NSCORE) return;
    unsigned k = g_keys[i];
    unsigned T = g_T;
    if (k > T) {
        int pos = atomicAdd(&g_cntHigh, 1);
        g_list[pos] = (((unsigned long long)k) << 32) |
                      (unsigned long long)(0xFFFFFFFFu - (unsigned)i);
    } else if (k == T) {
        int pos = atomicAdd(&g_cntEq, 1);
        if (pos < 8192) g_tieIdx[pos] = (unsigned)i;
    }
}

/* sort tie indices ascending (bitonic bounded by next-pow2), append, pad */
__global__ void finalize_kernel() {
    __shared__ unsigned sIdx[8192];
    int t = threadIdx.x;
    int cnt = g_cntEq; if (cnt > 8192) cnt = 8192;
    int need = PRE - g_nAbove;
    int n2 = 32;
    while (n2 < cnt) n2 <<= 1;
    for (int i = t; i < n2; i += 1024) sIdx[i] = (i < cnt) ? g_tieIdx[i] : 0xFFFFFFFFu;
    __syncthreads();
    for (int k = 2; k <= n2; k <<= 1)
        for (int j = k >> 1; j > 0; j >>= 1) {
            for (int i = t; i < n2; i += 1024) {
                int l = i ^ j;
                if (l > i) {
                    unsigned a = sIdx[i], b = sIdx[l];
                    bool up = ((i & k) == 0);
                    if ((a > b) == up) { sIdx[i] = b; sIdx[l] = a; }
                }
            }
            __syncthreads();
        }
    unsigned T = g_T;
    int nA = g_nAbove;
    for (int j = t; j < need; j += 1024)
        g_list[nA + j] = (((unsigned long long)T) << 32) |
                         (unsigned long long)(0xFFFFFFFFu - sIdx[j]);
    for (int j = PRE + t; j < 8192; j += 1024) g_list[j] = 0ull;
}

/* descending bitonic sort of the 8192 composites (zeros sink to the end) */
__global__ void sort_kernel() {
    extern __shared__ unsigned long long sm[];
    int t = threadIdx.x;
    for (int i = t; i < 8192; i += 1024) sm[i] = g_list[i];
    __syncthreads();
    for (int k = 2; k <= 8192; k <<= 1)
        for (int j = k >> 1; j > 0; j >>= 1) {
            for (int i = t; i < 8192; i += 1024) {
                int l = i ^ j;
                if (l > i) {
                    unsigned long long a = sm[i], b = sm[l];
                    bool up = ((i & k) == 0);
                    if ((a < b) == up) { sm[i] = b; sm[l] = a; }
                }
            }
            __syncthreads();
        }
    for (int i = t; i < 8192; i += 1024) g_list[i] = sm[i];
}

/* ---------------- decode/clip — exact fp32, UNFUSED (match XLA) ------------ */
__global__ void decode_kernel(const float* __restrict__ anchors) {
    int j = blockIdx.x * blockDim.x + threadIdx.x;
    if (j >= PRE) return;
    unsigned long long comp = g_list[j];
    unsigned idx = 0xFFFFFFFFu - (unsigned)(comp & 0xFFFFFFFFull);
    float4 an = reinterpret_cast<const float4*>(anchors)[idx];
    float4 dl = reinterpret_cast<const float4*>(g_deltas)[idx];
    float wa = __fsub_rn(an.z, an.x);
    float ha = __fsub_rn(an.w, an.y);
    float xa = __fadd_rn(an.x, __fmul_rn(0.5f, wa));
    float ya = __fadd_rn(an.y, __fmul_rn(0.5f, ha));
    float dw = fminf(dl.z, BCLIP), dh = fminf(dl.w, BCLIP);
    float cx = __fadd_rn(__fmul_rn(dl.x, wa), xa);
    float cy = __fadd_rn(__fmul_rn(dl.y, ha), ya);
    float ew = (float)exp((double)dw);   /* exactly-rounded fp32 exp */
    float eh = (float)exp((double)dh);
    float wb = __fmul_rn(ew, wa);
    float hb = __fmul_rn(eh, ha);
    float x1 = __fsub_rn(cx, __fmul_rn(0.5f, wb));
    float y1 = __fsub_rn(cy, __fmul_rn(0.5f, hb));
    float x2 = __fadd_rn(cx, __fmul_rn(0.5f, wb));
    float y2 = __fadd_rn(cy, __fmul_rn(0.5f, hb));
    x1 = fminf(fmaxf(x1, 0.f), IMGSZ);
    y1 = fminf(fmaxf(y1, 0.f), IMGSZ);
    x2 = fminf(fmaxf(x2, 0.f), IMGSZ);
    y2 = fminf(fmaxf(y2, 0.f), IMGSZ);
    reinterpret_cast<float4*>(g_boxes)[j] = make_float4(x1, y1, x2, y2);
    g_valid[j] = (__fsub_rn(x2, x1) >= MINSZ) && (__fsub_rn(y2, y1) >= MINSZ);
}

/* ----------- NMS suppression mask — exact fp32, UNFUSED (match XLA) -------- */
__global__ void nms_mask_kernel() {
    int rb = blockIdx.y, cb = blockIdx.x;
    if (cb < rb) return;
    int t = threadIdx.x;
    __shared__ float4 cbox[64];
    int j0 = cb * 64;
    int jg = j0 + t;
    cbox[t] = (jg < PRE) ? reinterpret_cast<const float4*>(g_boxes)[jg]
                         : make_float4(0.f, 0.f, 0.f, 0.f);
    __syncthreads();
    int i = rb * 64 + t;
    if (i >= PRE) return;
    unsigned long long bits = 0ull;
    if (j0 + 63 > i) {
        float4 b = reinterpret_cast<const float4*>(g_boxes)[i];
        float a1 = __fmul_rn(__fsub_rn(b.z, b.x), __fsub_rn(b.w, b.y));
        int jmax = min(64, PRE - j0);
        for (int jj = 0; jj < jmax; jj++) {
            int j = j0 + jj;
            if (j <= i) continue;
            float4 c = cbox[jj];
            float lx = fmaxf(b.x, c.x), ly = fmaxf(b.y, c.y);
            float rx = fminf(b.z, c.z), ry = fminf(b.w, c.w);
            float iw = fmaxf(__fsub_rn(rx, lx), 0.f);
            float ih = fmaxf(__fsub_rn(ry, ly), 0.f);
            float inter = __fmul_rn(iw, ih);
            float a2 = __fmul_rn(__fsub_rn(c.z, c.x), __fsub_rn(c.w, c.y));
            float den = fmaxf(__fsub_rn(__fadd_rn(a1, a2), inter), 1e-6f);
            float iou = __fdiv_rn(inter, den);
            if (iou > NMS_THR) bits |= (1ull << jj);
        }
    }
    g_mask[(size_t)i * MASKW + cb] = bits;
}

/* ------ greedy scan: chunked smem prefetch (256 thr) + warp-0 serial ------- */
#define CHUNK 64
__global__ void nms_scan_kernel(float* __restrict__ out) {
    extern __shared__ unsigned long long sm2[];
    unsigned long long (*rows)[MASKW] =
        reinterpret_cast<unsigned long long (*)[MASKW]>(sm2);
    volatile unsigned long long* rem = sm2 + CHUNK * MASKW;  /* 94 words */
    __shared__ int s_nkept;
    int tid = threadIdx.x;
    for (int i = tid; i < POST * 4; i += 256) out[i] = 0.f;
    for (int w = tid; w < MASKW; w += 256) {
        unsigned long long m = 0ull;
        int base = w * 64;
        for (int k = 0; k < 64; k++) {
            int j = base + k;
            if (j >= PRE || !g_valid[j]) m |= (1ull << k);
        }
        rem[w] = m;
    }
    if (tid == 0) s_nkept = 0;
    __syncthreads();

    for (int c = 0; c < MASKW; c++) {
        int base_i = c * CHUNK;
        for (int idx = tid; idx < CHUNK * MASKW; idx += 256) {
            int rr = idx / MASKW, col = idx - rr * MASKW;
            int gi = base_i + rr;
            rows[rr][col] = (gi < PRE && col >= c) ? g_mask[(size_t)gi * MASKW + col] : 0ull;
        }
        __syncthreads();
        if (tid < 32) {
            int lane = tid;
            int nk = s_nkept;
            for (int bit = 0; bit < CHUNK; bit++) {
                int i = base_i + bit;
                if (i >= PRE || nk >= POST) break;
                if (!((rem[c] >> bit) & 1ull)) {
                    if (lane < 4) out[nk * 4 + lane] = g_boxes[i * 4 + lane];
                    nk++;
                    for (int w = c + lane; w < MASKW; w += 32)
                        rem[w] = rem[w] | rows[bit][w];
                    __syncwarp();
                }
            }
            if (lane == 0) s_nkept = nk;
        }
        __syncthreads();
        if (s_nkept >= POST) break;
        __syncthreads();
    }
}

/* --------------------------------- launch ---------------------------------- */
extern "C" void kernel_launch(void* const* d_in, const int* in_sizes, int n_in,
                              void* d_out, int out_size) {
    (void)in_sizes; (void)n_in; (void)out_size;
    const float* feature = (const float*)d_in[0];
    const float* anchors = (const float*)d_in[1];
    const float* w_conv  = (const float*)d_in[2];
    const float* b_conv  = (const float*)d_in[3];
    const float* w_obj   = (const float*)d_in[4];
    const float* b_obj   = (const float*)d_in[5];
    const float* w_reg   = (const float*)d_in[6];
    const float* b_reg   = (const float*)d_in[7];
    float* out = (float*)d_out;

    cudaFuncSetAttribute(sort_kernel, cudaFuncAttributeMaxDynamicSharedMemorySize, 65536);
    cudaFuncSetAttribute(nms_scan_kernel, cudaFuncAttributeMaxDynamicSharedMemorySize, 65536);

    prep_kernel<<<(KTOT * 256 + 255) / 256, 256>>>(w_conv);
    conv3x3_kernel<<<dim3(313, 2), 256>>>(feature, b_conv);
    heads_kernel<<<625, 192>>>(w_obj, b_obj, w_reg, b_reg);
    select_kernel<<<1, 1024>>>(0);
    hist2_kernel<<<1407, 256>>>();
    select_kernel<<<1, 1024>>>(1);
    compact_kernel<<<1407, 256>>>();
    finalize_kernel<<<1, 1024>>>();
    sort_kernel<<<1, 1024, 65536>>>();
    decode_kernel<<<24, 256>>>(anchors);
    nms_mask_kernel<<<dim3(94, 94), 64>>>();
    nms_scan_kernel<<<1, 256, (CHUNK * MASKW + MASKW) * 8>>>(out);
}

// round 13
// speedup vs baseline: 1.1394x; 1.0820x over previous
#include <cuda_runtime.h>
#include <math.h>
#include <stdint.h>

#define C_IN   256
#define HGT    200
#define WID    200
#define HWNUM  40000
#define NA     9
#define KTOT   2304
#define NSCORE 360000
#define PRE    6000
#define POST   1000
#define IMGSZ  1600.0f
#define NMS_THR 0.7f
#define MINSZ  1.0f
#define BCLIP  4.135166556742356f   /* log(1000/16) */
#define MASKW  94                   /* ceil(6000/64) */

/* ------------------------- scratch (device globals) ------------------------ */
__device__ float              g_wT[KTOT * 256];           /* w transposed: [k'][m] */
__device__ float              g_t[C_IN * HWNUM];          /* conv output (relu'd) */
__device__ unsigned int       g_keys[NSCORE];             /* monotone score keys  */
__device__ float              g_deltas[NSCORE * 4];
__device__ int                g_hist1[65536];
__device__ int                g_seg[1024];
__device__ int                g_selHigh;
__device__ int                g_cntHigh;
__device__ unsigned long long g_list[8192];               /* (key<<32)|(~idx)     */
__device__ float              g_boxes[PRE * 4];
__device__ int                g_valid[PRE];
__device__ unsigned long long g_mask[(size_t)PRE * MASKW];

/* --------------------------------- zero ----------------------------------- */
__global__ void zero_kernel() {
    int i = blockIdx.x * blockDim.x + threadIdx.x;
    if (i < 65536) g_hist1[i] = 0;
    if (i < 8192)  g_list[i] = 0ull;
    if (i == 0)    g_cntHigh = 0;
}

/* ------------- one-time weight transpose: wT[k'][m], k'=(rs,ci) ------------ */
__global__ void transpose_w_kernel(const float* __restrict__ w) {
    int idx = blockIdx.x * blockDim.x + threadIdx.x;   /* write-coalesced in m */
    if (idx >= KTOT * 256) return;
    int kp = idx >> 8;          /* k' = rs*256 + ci */
    int m  = idx & 255;
    int ci = kp & 255;
    int rs = kp >> 8;
    g_wT[idx] = w[(size_t)m * KTOT + ci * 9 + rs];
}

/* ---- 3x3 conv (implicit GEMM, sequential FMA over k' = (r,s,ci) order) ---- */
/* Bit-exact anchor preserved: each output element accumulates k'=0..2303      */
/* strictly in order (f32x2 halves round RN identically to scalar FFMA).       */
__global__ __launch_bounds__(256, 2)
void conv3x3_kernel(const float* __restrict__ x, const float* __restrict__ bias) {
    __shared__ __align__(16) float As[2][8][128];
    __shared__ __align__(16) float Bs[2][8][128];
    const int tid = threadIdx.x;
    const int m0 = blockIdx.y * 128;
    const int p0 = blockIdx.x * 128;
    const int kr = tid >> 5;           /* 0..7   : k-row within tile   */
    const int lc = (tid & 31) * 4;     /* 0..124 : column (m or p)     */
    const int tx = tid & 15, ty = tid >> 4;

    float4 aReg = make_float4(0.f, 0.f, 0.f, 0.f);
    float4 bReg = make_float4(0.f, 0.f, 0.f, 0.f);

    auto loadTiles = [&](int it) {
        int k0 = it * 8;
        aReg = *reinterpret_cast<const float4*>(&g_wT[(size_t)(k0 + kr) * 256 + m0 + lc]);
        int kp = k0 + kr;
        int rs = kp >> 8;
        int ci = kp & 255;
        int r = rs / 3 - 1;
        int s = rs - (rs / 3) * 3 - 1;
        const float* base = x + (size_t)ci * HWNUM;
        float bv[4];
#pragma unroll
        for (int jj = 0; jj < 4; jj++) {
            int p = p0 + lc + jj;
            float v = 0.f;
            if (p < HWNUM) {
                int h = p / 200;
                int wc = p - h * 200;
                int hh = h + r, wcc = wc + s;
                if (hh >= 0 && hh < HGT && wcc >= 0 && wcc < WID)
                    v = base[hh * WID + wcc];
            }
            bv[jj] = v;
        }
        bReg = make_float4(bv[0], bv[1], bv[2], bv[3]);
    };
    auto storeTiles = [&](int buf) {
        *reinterpret_cast<float4*>(&As[buf][kr][lc]) = aReg;
        *reinterpret_cast<float4*>(&Bs[buf][kr][lc]) = bReg;
    };

    unsigned long long acc2[8][4];
#pragma unroll
    for (int i = 0; i < 8; i++)
#pragma unroll
        for (int j = 0; j < 4; j++) acc2[i][j] = 0ull;

    loadTiles(0);
    storeTiles(0);
    __syncthreads();
    int cur = 0;
    const int NIT = KTOT / 8;  /* 288 */
    for (int it = 0; it < NIT; it++) {
        if (it + 1 < NIT) loadTiles(it + 1);
#pragma unroll
        for (int kk = 0; kk < 8; kk++) {
            float4 a0 = *reinterpret_cast<const float4*>(&As[cur][kk][ty * 8]);
            float4 a1 = *reinterpret_cast<const float4*>(&As[cur][kk][ty * 8 + 4]);
            ulonglong2 bb0 = *reinterpret_cast<const ulonglong2*>(&Bs[cur][kk][tx * 4]);
            ulonglong2 bb1 = *reinterpret_cast<const ulonglong2*>(&Bs[cur][kk][64 + tx * 4]);
            unsigned long long b2[4] = {bb0.x, bb0.y, bb1.x, bb1.y};
            float av[8] = {a0.x, a0.y, a0.z, a0.w, a1.x, a1.y, a1.z, a1.w};
            unsigned long long a2[8];
#pragma unroll
            for (int i = 0; i < 8; i++) {
                unsigned ai = __float_as_uint(av[i]);
                asm("mov.b64 %0, {%1, %1};" : "=l"(a2[i]) : "r"(ai));
            }
#pragma unroll
            for (int i = 0; i < 8; i++)
#pragma unroll
                for (int j = 0; j < 4; j++)
                    asm("fma.rn.f32x2 %0, %1, %2, %3;"
                        : "=l"(acc2[i][j])
                        : "l"(a2[i]), "l"(b2[j]), "l"(acc2[i][j]));
        }
        if (it + 1 < NIT) {
            storeTiles(cur ^ 1);
            __syncthreads();
            cur ^= 1;
        }
    }
    /* epilogue: unpack pairs; columns p0+tx*4 (j 0-1) and p0+64+tx*4 (j 2-3) */
#pragma unroll
    for (int i = 0; i < 8; i++) {
        int m = m0 + ty * 8 + i;
        float bv = bias[m];
        float v[8];
#pragma unroll
        for (int j = 0; j < 4; j++) {
            unsigned lo, hi;
            asm("mov.b64 {%0, %1}, %2;" : "=r"(lo), "=r"(hi) : "l"(acc2[i][j]));
            v[j * 2 + 0] = __uint_as_float(lo);
            v[j * 2 + 1] = __uint_as_float(hi);
        }
        float4 o0, o1;
        o0.x = fmaxf(__fadd_rn(v[0], bv), 0.f);
        o0.y = fmaxf(__fadd_rn(v[1], bv), 0.f);
        o0.z = fmaxf(__fadd_rn(v[2], bv), 0.f);
        o0.w = fmaxf(__fadd_rn(v[3], bv), 0.f);
        o1.x = fmaxf(__fadd_rn(v[4], bv), 0.f);
        o1.y = fmaxf(__fadd_rn(v[5], bv), 0.f);
        o1.z = fmaxf(__fadd_rn(v[6], bv), 0.f);
        o1.w = fmaxf(__fadd_rn(v[7], bv), 0.f);
        int pA = p0 + tx * 4;
        int pB = p0 + 64 + tx * 4;
        if (pA < HWNUM) *reinterpret_cast<float4*>(&g_t[(size_t)m * HWNUM + pA]) = o0;
        if (pB < HWNUM) *reinterpret_cast<float4*>(&g_t[(size_t)m * HWNUM + pB]) = o1;
    }
}

/* --- 1x1 heads (plain sequential FMA) + fused hist1; 128 thr, 313 blocks --- */
__global__ __launch_bounds__(128)
void heads_kernel(const float* __restrict__ wObj, const float* __restrict__ bObj,
                  const float* __restrict__ wReg, const float* __restrict__ bReg) {
    __shared__ float ws[45 * 256];
    __shared__ float bs[45];
    int tid = threadIdx.x;
    for (int i = tid; i < 9 * 256; i += 128) ws[i] = wObj[i];
    for (int i = tid; i < 36 * 256; i += 128) ws[9 * 256 + i] = wReg[i];
    if (tid < 9) bs[tid] = bObj[tid];
    if (tid < 36) bs[9 + tid] = bReg[tid];
    __syncthreads();

    int p = blockIdx.x * 128 + tid;
    if (p >= HWNUM) return;
    float acc[45];
#pragma unroll
    for (int o = 0; o < 45; o++) acc[o] = 0.f;
#pragma unroll 4
    for (int ci = 0; ci < 256; ci++) {
        float a = g_t[(size_t)ci * HWNUM + p];
#pragma unroll
        for (int o = 0; o < 45; o++)
            acc[o] = fmaf(a, ws[o * 256 + ci], acc[o]);
    }
#pragma unroll
    for (int a = 0; a < 9; a++) {
        float s = __fadd_rn(acc[a], bs[a]);
        unsigned u = __float_as_uint(s);
        unsigned key = (u & 0x80000000u) ? ~u : (u | 0x80000000u);
        g_keys[p * 9 + a] = key;
        atomicAdd(&g_hist1[key >> 16], 1);
    }
#pragma unroll
    for (int c = 0; c < 36; c++)
        g_deltas[(size_t)p * 36 + c] = __fadd_rn(acc[9 + c], bs[9 + c]);
}

/* ------ segment sums: 1024 segments x 64 bins, int4 loads, 16 SMs ---------- */
__global__ void segsum_kernel() {
    int seg = blockIdx.x * 64 + threadIdx.x;   /* <<<16,64>>> : 0..1023 */
    int lo = 65536 - seg * 64 - 64;
    int s = 0;
#pragma unroll
    for (int k = 0; k < 16; k++) {
        int4 v = *reinterpret_cast<const int4*>(&g_hist1[lo + k * 4]);
        s += v.x + v.y + v.z + v.w;
    }
    g_seg[seg] = s;
}

/* ---- select: scan 1024 segsums, crossing thread walks its 64 bins --------- */
__global__ void select_kernel() {
    __shared__ int csum[1024];
    int t = threadIdx.x;
    int s = g_seg[t];
    csum[t] = s;
    __syncthreads();
    for (int off = 1; off < 1024; off <<= 1) {
        int v = (t >= off) ? csum[t - off] : 0;
        __syncthreads();
        csum[t] += v;
        __syncthreads();
    }
    int incl = csum[t];
    int excl = incl - s;
    if (excl < PRE && incl >= PRE) {
        int start = t * 64;
        int lo = 65536 - start - 64;
        int vals[64];
#pragma unroll
        for (int k4 = 0; k4 < 16; k4++) {
            int4 v = *reinterpret_cast<const int4*>(&g_hist1[lo + k4 * 4]);
            vals[k4 * 4 + 0] = v.x;
            vals[k4 * 4 + 1] = v.y;
            vals[k4 * 4 + 2] = v.z;
            vals[k4 * 4 + 3] = v.w;
        }
        int acc = excl;
#pragma unroll
        for (int k = 0; k < 64; k++) {
            int c = vals[63 - k];
            if (acc + c >= PRE) { g_selHigh = 65535 - (start + k); break; }
            acc += c;
        }
    }
}

/* ------- compact: all keys with high16 >= selHigh, as 64-bit composites ----- */
__global__ void compact_kernel() {
    int i = blockIdx.x * blockDim.x + threadIdx.x;
    if (i >= NSCORE) return;
    unsigned k = g_keys[i];
    if ((int)(k >> 16) >= g_selHigh) {
        int pos = atomicAdd(&g_cntHigh, 1);
        if (pos < 8192)
            g_list[pos] = (((unsigned long long)k) << 32) |
                          (unsigned long long)(0xFFFFFFFFu - (unsigned)i);
    }
}

/* descending bitonic sort of the 8192 composites (zeros sink to the end); the */
/* first PRE entries afterwards are exactly lax.top_k order (key desc,idx asc) */
__global__ void sort_kernel() {
    extern __shared__ unsigned long long sm[];
    int t = threadIdx.x;
    for (int i = t; i < 8192; i += 1024) sm[i] = g_list[i];
    __syncthreads();
    for (int k = 2; k <= 8192; k <<= 1)
        for (int j = k >> 1; j > 0; j >>= 1) {
            for (int i = t; i < 8192; i += 1024) {
                int l = i ^ j;
                if (l > i) {
                    unsigned long long a = sm[i], b = sm[l];
                    bool up = ((i & k) == 0);
                    if ((a < b) == up) { sm[i] = b; sm[l] = a; }
                }
            }
            __syncthreads();
        }
    for (int i = t; i < 8192; i += 1024) g_list[i] = sm[i];
}

/* ---------------- decode/clip — exact fp32, UNFUSED (match XLA) ------------ */
__global__ void decode_kernel(const float* __restrict__ anchors) {
    int j = blockIdx.x * blockDim.x + threadIdx.x;
    if (j >= PRE) return;
    unsigned long long comp = g_list[j];
    unsigned idx = 0xFFFFFFFFu - (unsigned)(comp & 0xFFFFFFFFull);
    float4 an = reinterpret_cast<const float4*>(anchors)[idx];
    float4 dl = reinterpret_cast<const float4*>(g_deltas)[idx];
    float wa = __fsub_rn(an.z, an.x);
    float ha = __fsub_rn(an.w, an.y);
    float xa = __fadd_rn(an.x, __fmul_rn(0.5f, wa));
    float ya = __fadd_rn(an.y, __fmul_rn(0.5f, ha));
    float dw = fminf(dl.z, BCLIP), dh = fminf(dl.w, BCLIP);
    float cx = __fadd_rn(__fmul_rn(dl.x, wa), xa);
    float cy = __fadd_rn(__fmul_rn(dl.y, ha), ya);
    float ew = (float)exp((double)dw);   /* exactly-rounded fp32 exp */
    float eh = (float)exp((double)dh);
    float wb = __fmul_rn(ew, wa);
    float hb = __fmul_rn(eh, ha);
    float x1 = __fsub_rn(cx, __fmul_rn(0.5f, wb));
    float y1 = __fsub_rn(cy, __fmul_rn(0.5f, hb));
    float x2 = __fadd_rn(cx, __fmul_rn(0.5f, wb));
    float y2 = __fadd_rn(cy, __fmul_rn(0.5f, hb));
    x1 = fminf(fmaxf(x1, 0.f), IMGSZ);
    y1 = fminf(fmaxf(y1, 0.f), IMGSZ);
    x2 = fminf(fmaxf(x2, 0.f), IMGSZ);
    y2 = fminf(fmaxf(y2, 0.f), IMGSZ);
    reinterpret_cast<float4*>(g_boxes)[j] = make_float4(x1, y1, x2, y2);
    g_valid[j] = (__fsub_rn(x2, x1) >= MINSZ) && (__fsub_rn(y2, y1) >= MINSZ);
}

/* ----------- NMS suppression mask — exact fp32, UNFUSED (match XLA) -------- */
__global__ void nms_mask_kernel() {
    int rb = blockIdx.y, cb = blockIdx.x;
    if (cb < rb) return;
    int t = threadIdx.x;
    __shared__ float4 cbox[64];
    int j0 = cb * 64;
    int jg = j0 + t;
    cbox[t] = (jg < PRE) ? reinterpret_cast<const float4*>(g_boxes)[jg]
                         : make_float4(0.f, 0.f, 0.f, 0.f);
    __syncthreads();
    int i = rb * 64 + t;
    if (i >= PRE) return;
    unsigned long long bits = 0ull;
    if (j0 + 63 > i) {
        float4 b = reinterpret_cast<const float4*>(g_boxes)[i];
        float a1 = __fmul_rn(__fsub_rn(b.z, b.x), __fsub_rn(b.w, b.y));
        int jmax = min(64, PRE - j0);
        for (int jj = 0; jj < jmax; jj++) {
            int j = j0 + jj;
            if (j <= i) continue;
            float4 c = cbox[jj];
            float lx = fmaxf(b.x, c.x), ly = fmaxf(b.y, c.y);
            float rx = fminf(b.z, c.z), ry = fminf(b.w, c.w);
            float iw = fmaxf(__fsub_rn(rx, lx), 0.f);
            float ih = fmaxf(__fsub_rn(ry, ly), 0.f);
            float inter = __fmul_rn(iw, ih);
            float a2 = __fmul_rn(__fsub_rn(c.z, c.x), __fsub_rn(c.w, c.y));
            float den = fmaxf(__fsub_rn(__fadd_rn(a1, a2), inter), 1e-6f);
            float iou = __fdiv_rn(inter, den);
            if (iou > NMS_THR) bits |= (1ull << jj);
        }
    }
    g_mask[(size_t)i * MASKW + cb] = bits;
}

/* ------ greedy scan: chunked smem prefetch (256 thr) + warp-0 serial ------- */
#define CHUNK 64
__global__ void nms_scan_kernel(float* __restrict__ out) {
    extern __shared__ unsigned long long sm2[];
    unsigned long long (*rows)[MASKW] =
        reinterpret_cast<unsigned long long (*)[MASKW]>(sm2);
    volatile unsigned long long* rem = sm2 + CHUNK * MASKW;  /* 94 words */
    __shared__ int s_nkept;
    int tid = threadIdx.x;
    for (int i = tid; i < POST * 4; i += 256) out[i] = 0.f;
    for (int w = tid; w < MASKW; w += 256) {
        unsigned long long m = 0ull;
        int base = w * 64;
        for (int k = 0; k < 64; k++) {
            int j = base + k;
            if (j >= PRE || !g_valid[j]) m |= (1ull << k);
        }
        rem[w] = m;
    }
    if (tid == 0) s_nkept = 0;
    __syncthreads();

    for (int c = 0; c < MASKW; c++) {
        int base_i = c * CHUNK;
        for (int idx = tid; idx < CHUNK * MASKW; idx += 256) {
            int rr = idx / MASKW, col = idx - rr * MASKW;
            int gi = base_i + rr;
            rows[rr][col] = (gi < PRE && col >= c) ? g_mask[(size_t)gi * MASKW + col] : 0ull;
        }
        __syncthreads();
        if (tid < 32) {
            int lane = tid;
            int nk = s_nkept;
            for (int bit = 0; bit < CHUNK; bit++) {
                int i = base_i + bit;
                if (i >= PRE || nk >= POST) break;
                if (!((rem[c] >> bit) & 1ull)) {
                    if (lane < 4) out[nk * 4 + lane] = g_boxes[i * 4 + lane];
                    nk++;
                    for (int w = c + lane; w < MASKW; w += 32)
                        rem[w] = rem[w] | rows[bit][w];
                    __syncwarp();
                }
            }
            if (lane == 0) s_nkept = nk;
        }
        __syncthreads();
        if (s_nkept >= POST) break;
        __syncthreads();
    }
}

/* --------------------------------- launch ---------------------------------- */
extern "C" void kernel_launch(void* const* d_in, const int* in_sizes, int n_in,
                              void* d_out, int out_size) {
    (void)in_sizes; (void)n_in; (void)out_size;
    const float* feature = (const float*)d_in[0];
    const float* anchors = (const float*)d_in[1];
    const float* w_conv  = (const float*)d_in[2];
    const float* b_conv  = (const float*)d_in[3];
    const float* w_obj   = (const float*)d_in[4];
    const float* b_obj   = (const float*)d_in[5];
    const float* w_reg   = (const float*)d_in[6];
    const float* b_reg   = (const float*)d_in[7];
    float* out = (float*)d_out;

    cudaFuncSetAttribute(sort_kernel, cudaFuncAttributeMaxDynamicSharedMemorySize, 65536);
    cudaFuncSetAttribute(nms_scan_kernel, cudaFuncAttributeMaxDynamicSharedMemorySize, 65536);

    zero_kernel<<<256, 256>>>();
    transpose_w_kernel<<<(KTOT * 256 + 255) / 256, 256>>>(w_conv);
    conv3x3_kernel<<<dim3(313, 2), 256>>>(feature, b_conv);
    heads_kernel<<<313, 128>>>(w_obj, b_obj, w_reg, b_reg);
    segsum_kernel<<<16, 64>>>();
    select_kernel<<<1, 1024>>>();
    compact_kernel<<<1407, 256>>>();
    sort_kernel<<<1, 1024, 65536>>>();
    decode_kernel<<<24, 256>>>(anchors);
    nms_mask_kernel<<<dim3(94, 94), 64>>>();
    nms_scan_kernel<<<1, 256, (CHUNK * MASKW + MASKW) * 8>>>(out);
}

// round 14
// speedup vs baseline: 1.2159x; 1.0672x over previous
#include <cuda_runtime.h>
#include <math.h>
#include <stdint.h>

#define C_IN   256
#define HGT    200
#define WID    200
#define HWNUM  40000
#define NA     9
#define KTOT   2304
#define NSCORE 360000
#define PRE    6000
#define POST   1000
#define IMGSZ  1600.0f
#define NMS_THR 0.7f
#define MINSZ  1.0f
#define BCLIP  4.135166556742356f   /* log(1000/16) */
#define MASKW  94                   /* ceil(6000/64) */

/* ------------------------- scratch (device globals) ------------------------ */
__device__ float              g_wT[KTOT * 256];           /* w transposed: [k'][m] */
__device__ float              g_t[C_IN * HWNUM];          /* conv output (relu'd) */
__device__ unsigned int       g_keys[NSCORE];             /* monotone score keys  */
__device__ float              g_deltas[NSCORE * 4];
__device__ int                g_hist1[65536];
__device__ int                g_seg[1024];
__device__ int                g_selHigh;
__device__ int                g_cntHigh;
__device__ unsigned long long g_list[8192];               /* (key<<32)|(~idx)     */
__device__ float              g_boxes[PRE * 4];
__device__ int                g_valid[PRE];
__device__ unsigned long long g_mask[(size_t)PRE * MASKW];

/* --------------------------------- zero ----------------------------------- */
__global__ void zero_kernel() {
    int i = blockIdx.x * blockDim.x + threadIdx.x;
    if (i < 65536) g_hist1[i] = 0;
    if (i < 8192)  g_list[i] = 0ull;
    if (i == 0)    g_cntHigh = 0;
}

/* ------------- one-time weight transpose: wT[k'][m], k'=(rs,ci) ------------ */
__global__ void transpose_w_kernel(const float* __restrict__ w) {
    int idx = blockIdx.x * blockDim.x + threadIdx.x;   /* write-coalesced in m */
    if (idx >= KTOT * 256) return;
    int kp = idx >> 8;          /* k' = rs*256 + ci */
    int m  = idx & 255;
    int ci = kp & 255;
    int rs = kp >> 8;
    g_wT[idx] = w[(size_t)m * KTOT + ci * 9 + rs];
}

/* ---- 3x3 conv (implicit GEMM, sequential FMA over k' = (r,s,ci) order) ---- */
/* Bit-exact anchor preserved: each output element accumulates k'=0..2303      */
/* strictly in order (f32x2 halves round RN identically to scalar FFMA).       */
__global__ __launch_bounds__(256, 2)
void conv3x3_kernel(const float* __restrict__ x, const float* __restrict__ bias) {
    __shared__ __align__(16) float As[2][8][128];
    __shared__ __align__(16) float Bs[2][8][128];
    const int tid = threadIdx.x;
    const int m0 = blockIdx.y * 128;
    const int p0 = blockIdx.x * 128;
    const int kr = tid >> 5;           /* 0..7   : k-row within tile   */
    const int lc = (tid & 31) * 4;     /* 0..124 : column (m or p)     */
    const int tx = tid & 15, ty = tid >> 4;

    float4 aReg = make_float4(0.f, 0.f, 0.f, 0.f);
    float4 bReg = make_float4(0.f, 0.f, 0.f, 0.f);

    auto loadTiles = [&](int it) {
        int k0 = it * 8;
        aReg = *reinterpret_cast<const float4*>(&g_wT[(size_t)(k0 + kr) * 256 + m0 + lc]);
        int kp = k0 + kr;
        int rs = kp >> 8;
        int ci = kp & 255;
        int r = rs / 3 - 1;
        int s = rs - (rs / 3) * 3 - 1;
        const float* base = x + (size_t)ci * HWNUM;
        float bv[4];
#pragma unroll
        for (int jj = 0; jj < 4; jj++) {
            int p = p0 + lc + jj;
            float v = 0.f;
            if (p < HWNUM) {
                int h = p / 200;
                int wc = p - h * 200;
                int hh = h + r, wcc = wc + s;
                if (hh >= 0 && hh < HGT && wcc >= 0 && wcc < WID)
                    v = base[hh * WID + wcc];
            }
            bv[jj] = v;
        }
        bReg = make_float4(bv[0], bv[1], bv[2], bv[3]);
    };
    auto storeTiles = [&](int buf) {
        *reinterpret_cast<float4*>(&As[buf][kr][lc]) = aReg;
        *reinterpret_cast<float4*>(&Bs[buf][kr][lc]) = bReg;
    };

    unsigned long long acc2[8][4];
#pragma unroll
    for (int i = 0; i < 8; i++)
#pragma unroll
        for (int j = 0; j < 4; j++) acc2[i][j] = 0ull;

    loadTiles(0);
    storeTiles(0);
    __syncthreads();
    int cur = 0;
    const int NIT = KTOT / 8;  /* 288 */
    for (int it = 0; it < NIT; it++) {
        if (it + 1 < NIT) loadTiles(it + 1);
#pragma unroll
        for (int kk = 0; kk < 8; kk++) {
            float4 a0 = *reinterpret_cast<const float4*>(&As[cur][kk][ty * 8]);
            float4 a1 = *reinterpret_cast<const float4*>(&As[cur][kk][ty * 8 + 4]);
            ulonglong2 bb0 = *reinterpret_cast<const ulonglong2*>(&Bs[cur][kk][tx * 4]);
            ulonglong2 bb1 = *reinterpret_cast<const ulonglong2*>(&Bs[cur][kk][64 + tx * 4]);
            unsigned long long b2[4] = {bb0.x, bb0.y, bb1.x, bb1.y};
            float av[8] = {a0.x, a0.y, a0.z, a0.w, a1.x, a1.y, a1.z, a1.w};
            unsigned long long a2[8];
#pragma unroll
            for (int i = 0; i < 8; i++) {
                unsigned ai = __float_as_uint(av[i]);
                asm("mov.b64 %0, {%1, %1};" : "=l"(a2[i]) : "r"(ai));
            }
#pragma unroll
            for (int i = 0; i < 8; i++)
#pragma unroll
                for (int j = 0; j < 4; j++)
                    asm("fma.rn.f32x2 %0, %1, %2, %3;"
                        : "=l"(acc2[i][j])
                        : "l"(a2[i]), "l"(b2[j]), "l"(acc2[i][j]));
        }
        if (it + 1 < NIT) {
            storeTiles(cur ^ 1);
            __syncthreads();
            cur ^= 1;
        }
    }
    /* epilogue: unpack pairs; columns p0+tx*4 (j 0-1) and p0+64+tx*4 (j 2-3) */
#pragma unroll
    for (int i = 0; i < 8; i++) {
        int m = m0 + ty * 8 + i;
        float bv = bias[m];
        float v[8];
#pragma unroll
        for (int j = 0; j < 4; j++) {
            unsigned lo, hi;
            asm("mov.b64 {%0, %1}, %2;" : "=r"(lo), "=r"(hi) : "l"(acc2[i][j]));
            v[j * 2 + 0] = __uint_as_float(lo);
            v[j * 2 + 1] = __uint_as_float(hi);
        }
        float4 o0, o1;
        o0.x = fmaxf(__fadd_rn(v[0], bv), 0.f);
        o0.y = fmaxf(__fadd_rn(v[1], bv), 0.f);
        o0.z = fmaxf(__fadd_rn(v[2], bv), 0.f);
        o0.w = fmaxf(__fadd_rn(v[3], bv), 0.f);
        o1.x = fmaxf(__fadd_rn(v[4], bv), 0.f);
        o1.y = fmaxf(__fadd_rn(v[5], bv), 0.f);
        o1.z = fmaxf(__fadd_rn(v[6], bv), 0.f);
        o1.w = fmaxf(__fadd_rn(v[7], bv), 0.f);
        int pA = p0 + tx * 4;
        int pB = p0 + 64 + tx * 4;
        if (pA < HWNUM) *reinterpret_cast<float4*>(&g_t[(size_t)m * HWNUM + pA]) = o0;
        if (pB < HWNUM) *reinterpret_cast<float4*>(&g_t[(size_t)m * HWNUM + pB]) = o1;
    }
}

/* --- 1x1 heads: 2 pixels/thread ILP (each channel still sequential in ci) -- */
__global__ __launch_bounds__(64)
void heads_kernel(const float* __restrict__ wObj, const float* __restrict__ bObj,
                  const float* __restrict__ wReg, const float* __restrict__ bReg) {
    __shared__ float ws[45 * 256];
    __shared__ float bs[45];
    int tid = threadIdx.x;   /* 64 threads */
    for (int i = tid; i < 9 * 256; i += 64) ws[i] = wObj[i];
    for (int i = tid; i < 36 * 256; i += 64) ws[9 * 256 + i] = wReg[i];
    if (tid < 9) bs[tid] = bObj[tid];
    if (tid < 36) bs[9 + tid] = bReg[tid];
    __syncthreads();

    int p0 = blockIdx.x * 128 + tid;
    int p1 = p0 + 64;
    bool v0 = p0 < HWNUM, v1 = p1 < HWNUM;
    float acc0[45], acc1[45];
#pragma unroll
    for (int o = 0; o < 45; o++) { acc0[o] = 0.f; acc1[o] = 0.f; }
#pragma unroll 4
    for (int ci = 0; ci < 256; ci++) {
        float a0 = v0 ? g_t[(size_t)ci * HWNUM + p0] : 0.f;
        float a1 = v1 ? g_t[(size_t)ci * HWNUM + p1] : 0.f;
#pragma unroll
        for (int o = 0; o < 45; o++) {
            float wv = ws[o * 256 + ci];
            acc0[o] = fmaf(a0, wv, acc0[o]);
            acc1[o] = fmaf(a1, wv, acc1[o]);
        }
    }
    if (v0) {
#pragma unroll
        for (int a = 0; a < 9; a++) {
            float s = __fadd_rn(acc0[a], bs[a]);
            unsigned u = __float_as_uint(s);
            unsigned key = (u & 0x80000000u) ? ~u : (u | 0x80000000u);
            g_keys[p0 * 9 + a] = key;
            atomicAdd(&g_hist1[key >> 16], 1);
        }
#pragma unroll
        for (int c = 0; c < 36; c++)
            g_deltas[(size_t)p0 * 36 + c] = __fadd_rn(acc0[9 + c], bs[9 + c]);
    }
    if (v1) {
#pragma unroll
        for (int a = 0; a < 9; a++) {
            float s = __fadd_rn(acc1[a], bs[a]);
            unsigned u = __float_as_uint(s);
            unsigned key = (u & 0x80000000u) ? ~u : (u | 0x80000000u);
            g_keys[p1 * 9 + a] = key;
            atomicAdd(&g_hist1[key >> 16], 1);
        }
#pragma unroll
        for (int c = 0; c < 36; c++)
            g_deltas[(size_t)p1 * 36 + c] = __fadd_rn(acc1[9 + c], bs[9 + c]);
    }
}

/* ------ segment sums: 1024 segments x 64 bins, int4 loads, 16 SMs ---------- */
__global__ void segsum_kernel() {
    int seg = blockIdx.x * 64 + threadIdx.x;   /* <<<16,64>>> : 0..1023 */
    int lo = 65536 - seg * 64 - 64;
    int s = 0;
#pragma unroll
    for (int k = 0; k < 16; k++) {
        int4 v = *reinterpret_cast<const int4*>(&g_hist1[lo + k * 4]);
        s += v.x + v.y + v.z + v.w;
    }
    g_seg[seg] = s;
}

/* ---- select: scan 1024 segsums, crossing thread walks its 64 bins --------- */
__global__ void select_kernel() {
    __shared__ int csum[1024];
    int t = threadIdx.x;
    int s = g_seg[t];
    csum[t] = s;
    __syncthreads();
    for (int off = 1; off < 1024; off <<= 1) {
        int v = (t >= off) ? csum[t - off] : 0;
        __syncthreads();
        csum[t] += v;
        __syncthreads();
    }
    int incl = csum[t];
    int excl = incl - s;
    if (excl < PRE && incl >= PRE) {
        int start = t * 64;
        int lo = 65536 - start - 64;
        int vals[64];
#pragma unroll
        for (int k4 = 0; k4 < 16; k4++) {
            int4 v = *reinterpret_cast<const int4*>(&g_hist1[lo + k4 * 4]);
            vals[k4 * 4 + 0] = v.x;
            vals[k4 * 4 + 1] = v.y;
            vals[k4 * 4 + 2] = v.z;
            vals[k4 * 4 + 3] = v.w;
        }
        int acc = excl;
#pragma unroll
        for (int k = 0; k < 64; k++) {
            int c = vals[63 - k];
            if (acc + c >= PRE) { g_selHigh = 65535 - (start + k); break; }
            acc += c;
        }
    }
}

/* ------- compact: all keys with high16 >= selHigh, as 64-bit composites ----- */
__global__ void compact_kernel() {
    int i = blockIdx.x * blockDim.x + threadIdx.x;
    if (i >= NSCORE) return;
    unsigned k = g_keys[i];
    if ((int)(k >> 16) >= g_selHigh) {
        int pos = atomicAdd(&g_cntHigh, 1);
        if (pos < 8192)
            g_list[pos] = (((unsigned long long)k) << 32) |
                          (unsigned long long)(0xFFFFFFFFu - (unsigned)i);
    }
}

/* descending bitonic sort of the 8192 composites (zeros sink to the end); the */
/* first PRE entries afterwards are exactly lax.top_k order (key desc,idx asc) */
__global__ void sort_kernel() {
    extern __shared__ unsigned long long sm[];
    int t = threadIdx.x;
    for (int i = t; i < 8192; i += 1024) sm[i] = g_list[i];
    __syncthreads();
    for (int k = 2; k <= 8192; k <<= 1)
        for (int j = k >> 1; j > 0; j >>= 1) {
            for (int i = t; i < 8192; i += 1024) {
                int l = i ^ j;
                if (l > i) {
                    unsigned long long a = sm[i], b = sm[l];
                    bool up = ((i & k) == 0);
                    if ((a < b) == up) { sm[i] = b; sm[l] = a; }
                }
            }
            __syncthreads();
        }
    for (int i = t; i < 8192; i += 1024) g_list[i] = sm[i];
}

/* ---------------- decode/clip — exact fp32, UNFUSED (match XLA) ------------ */
__global__ void decode_kernel(const float* __restrict__ anchors) {
    int j = blockIdx.x * blockDim.x + threadIdx.x;
    if (j >= PRE) return;
    unsigned long long comp = g_list[j];
    unsigned idx = 0xFFFFFFFFu - (unsigned)(comp & 0xFFFFFFFFull);
    float4 an = reinterpret_cast<const float4*>(anchors)[idx];
    float4 dl = reinterpret_cast<const float4*>(g_deltas)[idx];
    float wa = __fsub_rn(an.z, an.x);
    float ha = __fsub_rn(an.w, an.y);
    float xa = __fadd_rn(an.x, __fmul_rn(0.5f, wa));
    float ya = __fadd_rn(an.y, __fmul_rn(0.5f, ha));
    float dw = fminf(dl.z, BCLIP), dh = fminf(dl.w, BCLIP);
    float cx = __fadd_rn(__fmul_rn(dl.x, wa), xa);
    float cy = __fadd_rn(__fmul_rn(dl.y, ha), ya);
    float ew = (float)exp((double)dw);   /* exactly-rounded fp32 exp */
    float eh = (float)exp((double)dh);
    float wb = __fmul_rn(ew, wa);
    float hb = __fmul_rn(eh, ha);
    float x1 = __fsub_rn(cx, __fmul_rn(0.5f, wb));
    float y1 = __fsub_rn(cy, __fmul_rn(0.5f, hb));
    float x2 = __fadd_rn(cx, __fmul_rn(0.5f, wb));
    float y2 = __fadd_rn(cy, __fmul_rn(0.5f, hb));
    x1 = fminf(fmaxf(x1, 0.f), IMGSZ);
    y1 = fminf(fmaxf(y1, 0.f), IMGSZ);
    x2 = fminf(fmaxf(x2, 0.f), IMGSZ);
    y2 = fminf(fmaxf(y2, 0.f), IMGSZ);
    reinterpret_cast<float4*>(g_boxes)[j] = make_float4(x1, y1, x2, y2);
    g_valid[j] = (__fsub_rn(x2, x1) >= MINSZ) && (__fsub_rn(y2, y1) >= MINSZ);
}

/* ----------- NMS suppression mask — exact fp32, UNFUSED (match XLA) -------- */
__global__ void nms_mask_kernel() {
    int rb = blockIdx.y, cb = blockIdx.x;
    if (cb < rb) return;
    int t = threadIdx.x;
    __shared__ float4 cbox[64];
    int j0 = cb * 64;
    int jg = j0 + t;
    cbox[t] = (jg < PRE) ? reinterpret_cast<const float4*>(g_boxes)[jg]
                         : make_float4(0.f, 0.f, 0.f, 0.f);
    __syncthreads();
    int i = rb * 64 + t;
    if (i >= PRE) return;
    unsigned long long bits = 0ull;
    if (j0 + 63 > i) {
        float4 b = reinterpret_cast<const float4*>(g_boxes)[i];
        float a1 = __fmul_rn(__fsub_rn(b.z, b.x), __fsub_rn(b.w, b.y));
        int jmax = min(64, PRE - j0);
        for (int jj = 0; jj < jmax; jj++) {
            int j = j0 + jj;
            if (j <= i) continue;
            float4 c = cbox[jj];
            float lx = fmaxf(b.x, c.x), ly = fmaxf(b.y, c.y);
            float rx = fminf(b.z, c.z), ry = fminf(b.w, c.w);
            float iw = fmaxf(__fsub_rn(rx, lx), 0.f);
            float ih = fmaxf(__fsub_rn(ry, ly), 0.f);
            float inter = __fmul_rn(iw, ih);
            float a2 = __fmul_rn(__fsub_rn(c.z, c.x), __fsub_rn(c.w, c.y));
            float den = fmaxf(__fsub_rn(__fadd_rn(a1, a2), inter), 1e-6f);
            float iou = __fdiv_rn(inter, den);
            if (iou > NMS_THR) bits |= (1ull << jj);
        }
    }
    g_mask[(size_t)i * MASKW + cb] = bits;
}

/* -- greedy scan: double-buffered prefetch, smem-only critical chain, -------
   deferred parallel output of kept boxes                                     */
#define CHUNK 64
__global__ void nms_scan_kernel(float* __restrict__ out) {
    extern __shared__ unsigned long long sm2[];
    unsigned long long* bufA = sm2;                       /* CHUNK*MASKW      */
    unsigned long long* bufB = sm2 + CHUNK * MASKW;       /* CHUNK*MASKW      */
    volatile unsigned long long* rem = sm2 + 2 * CHUNK * MASKW;   /* MASKW    */
    int* kept = (int*)(sm2 + 2 * CHUNK * MASKW + MASKW);  /* POST ints        */
    __shared__ int s_nkept;
    int tid = threadIdx.x;   /* 256 threads */

    for (int i = tid; i < POST * 4; i += 256) out[i] = 0.f;
    for (int w = tid; w < MASKW; w += 256) {
        unsigned long long m = 0ull;
        int base = w * 64;
        for (int k = 0; k < 64; k++) {
            int j = base + k;
            if (j >= PRE || !g_valid[j]) m |= (1ull << k);
        }
        rem[w] = m;
    }
    if (tid == 0) s_nkept = 0;
    /* prefetch chunk 0 into bufA (all threads) */
    for (int idx = tid; idx < CHUNK * MASKW; idx += 256) {
        int rr = idx / MASKW, col = idx - rr * MASKW;
        rows_init:;
        bufA[idx] = (rr < PRE) ? g_mask[(size_t)rr * MASKW + col] : 0ull;
    }
    __syncthreads();

    for (int c = 0; c < MASKW; c++) {
        unsigned long long* curb = (c & 1) ? bufB : bufA;
        unsigned long long* nxtb = (c & 1) ? bufA : bufB;
        if (tid >= 32) {
            /* warps 1-7: prefetch chunk c+1 (only words >= c+1 are ever read) */
            if (c + 1 < MASKW) {
                int base_i = (c + 1) * CHUNK;
                for (int idx = tid - 32; idx < CHUNK * MASKW; idx += 224) {
                    int rr = idx / MASKW, col = idx - rr * MASKW;
                    int gi = base_i + rr;
                    nxtb[idx] = (gi < PRE && col > c) ? g_mask[(size_t)gi * MASKW + col] : 0ull;
                }
            }
        } else {
            int lane = tid;
            int nk = s_nkept;
            int base_i = c * CHUNK;
            for (int bit = 0; bit < CHUNK; bit++) {
                int i = base_i + bit;
                if (i >= PRE || nk >= POST) break;
                if (!((rem[c] >> bit) & 1ull)) {
                    if (lane == 0) kept[nk] = i;
                    nk++;
                    const unsigned long long* row = &curb[bit * MASKW];
                    for (int w = c + lane; w < MASKW; w += 32)
                        rem[w] = rem[w] | row[w];
                    __syncwarp();
                }
            }
            if (lane == 0) s_nkept = nk;
        }
        __syncthreads();
        if (s_nkept >= POST) break;
    }
    __syncthreads();
    /* parallel output of kept boxes (no latency in the critical chain) */
    int nk = s_nkept;
    for (int idx = tid; idx < nk * 4; idx += 256) {
        int k = idx >> 2, j = idx & 3;
        out[idx] = g_boxes[kept[k] * 4 + j];
    }
}

/* --------------------------------- launch ---------------------------------- */
extern "C" void kernel_launch(void* const* d_in, const int* in_sizes, int n_in,
                              void* d_out, int out_size) {
    (void)in_sizes; (void)n_in; (void)out_size;
    const float* feature = (const float*)d_in[0];
    const float* anchors = (const float*)d_in[1];
    const float* w_conv  = (const float*)d_in[2];
    const float* b_conv  = (const float*)d_in[3];
    const float* w_obj   = (const float*)d_in[4];
    const float* b_obj   = (const float*)d_in[5];
    const float* w_reg   = (const float*)d_in[6];
    const float* b_reg   = (const float*)d_in[7];
    float* out = (float*)d_out;

    const int scan_smem = (2 * CHUNK * MASKW + MASKW) * 8 + POST * 4;
    cudaFuncSetAttribute(sort_kernel, cudaFuncAttributeMaxDynamicSharedMemorySize, 65536);
    cudaFuncSetAttribute(nms_scan_kernel, cudaFuncAttributeMaxDynamicSharedMemorySize, scan_smem);

    zero_kernel<<<256, 256>>>();
    transpose_w_kernel<<<(KTOT * 256 + 255) / 256, 256>>>(w_conv);
    conv3x3_kernel<<<dim3(313, 2), 256>>>(feature, b_conv);
    heads_kernel<<<313, 64>>>(w_obj, b_obj, w_reg, b_reg);
    segsum_kernel<<<16, 64>>>();
    select_kernel<<<1, 1024>>>();
    compact_kernel<<<1407, 256>>>();
    sort_kernel<<<1, 1024, 65536>>>();
    decode_kernel<<<24, 256>>>(anchors);
    nms_mask_kernel<<<dim3(94, 94), 64>>>();
    nms_scan_kernel<<<1, 256, scan_smem>>>(out);
}

// round 15
// speedup vs baseline: 1.2230x; 1.0059x over previous
#include <cuda_runtime.h>
#include <math.h>
#include <stdint.h>

#define C_IN   256
#define HGT    200
#define WID    200
#define HWNUM  40000
#define NA     9
#define KTOT   2304
#define NSCORE 360000
#define PRE    6000
#define POST   1000
#define IMGSZ  1600.0f
#define NMS_THR 0.7f
#define MINSZ  1.0f
#define BCLIP  4.135166556742356f   /* log(1000/16) */
#define MASKW  94                   /* ceil(6000/64) */

/* ------------------------- scratch (device globals) ------------------------ */
__device__ float              g_wT[KTOT * 256];           /* w transposed: [k'][m] */
__device__ float              g_t[C_IN * HWNUM];          /* conv output (relu'd) */
__device__ unsigned int       g_keys[NSCORE];             /* monotone score keys  */
__device__ float              g_deltas[NSCORE * 4];
__device__ int                g_hist1[65536];
__device__ int                g_seg[1024];
__device__ int                g_selHigh;
__device__ int                g_cntHigh;
__device__ unsigned long long g_list[8192];               /* (key<<32)|(~idx)     */
__device__ float              g_boxes[PRE * 4];
__device__ int                g_valid[PRE];
__device__ unsigned long long g_mask[(size_t)PRE * MASKW];

/* --------------------------------- zero ----------------------------------- */
__global__ void zero_kernel() {
    int i = blockIdx.x * blockDim.x + threadIdx.x;
    if (i < 65536) g_hist1[i] = 0;
    if (i < 8192)  g_list[i] = 0ull;
    if (i == 0)    g_cntHigh = 0;
}

/* ------------- one-time weight transpose: wT[k'][m], k'=(rs,ci) ------------ */
__global__ void transpose_w_kernel(const float* __restrict__ w) {
    int idx = blockIdx.x * blockDim.x + threadIdx.x;   /* write-coalesced in m */
    if (idx >= KTOT * 256) return;
    int kp = idx >> 8;          /* k' = rs*256 + ci */
    int m  = idx & 255;
    int ci = kp & 255;
    int rs = kp >> 8;
    g_wT[idx] = w[(size_t)m * KTOT + ci * 9 + rs];
}

/* ---- 3x3 conv (implicit GEMM, sequential FMA over k' = (r,s,ci) order) ---- */
/* Bit-exact anchor preserved: each output element accumulates k'=0..2303      */
/* strictly in order (f32x2 halves round RN identically to scalar FFMA).       */
__global__ __launch_bounds__(256, 2)
void conv3x3_kernel(const float* __restrict__ x, const float* __restrict__ bias) {
    __shared__ __align__(16) float As[2][8][128];
    __shared__ __align__(16) float Bs[2][8][128];
    const int tid = threadIdx.x;
    const int m0 = blockIdx.y * 128;
    const int p0 = blockIdx.x * 128;
    const int kr = tid >> 5;           /* 0..7   : k-row within tile   */
    const int lc = (tid & 31) * 4;     /* 0..124 : column (m or p)     */
    const int tx = tid & 15, ty = tid >> 4;

    float4 aReg = make_float4(0.f, 0.f, 0.f, 0.f);
    float4 bReg = make_float4(0.f, 0.f, 0.f, 0.f);

    auto loadTiles = [&](int it) {
        int k0 = it * 8;
        aReg = *reinterpret_cast<const float4*>(&g_wT[(size_t)(k0 + kr) * 256 + m0 + lc]);
        int kp = k0 + kr;
        int rs = kp >> 8;
        int ci = kp & 255;
        int r = rs / 3 - 1;
        int s = rs - (rs / 3) * 3 - 1;
        const float* base = x + (size_t)ci * HWNUM;
        float bv[4];
#pragma unroll
        for (int jj = 0; jj < 4; jj++) {
            int p = p0 + lc + jj;
            float v = 0.f;
            if (p < HWNUM) {
                int h = p / 200;
                int wc = p - h * 200;
                int hh = h + r, wcc = wc + s;
                if (hh >= 0 && hh < HGT && wcc >= 0 && wcc < WID)
                    v = base[hh * WID + wcc];
            }
            bv[jj] = v;
        }
        bReg = make_float4(bv[0], bv[1], bv[2], bv[3]);
    };
    auto storeTiles = [&](int buf) {
        *reinterpret_cast<float4*>(&As[buf][kr][lc]) = aReg;
        *reinterpret_cast<float4*>(&Bs[buf][kr][lc]) = bReg;
    };

    unsigned long long acc2[8][4];
#pragma unroll
    for (int i = 0; i < 8; i++)
#pragma unroll
        for (int j = 0; j < 4; j++) acc2[i][j] = 0ull;

    loadTiles(0);
    storeTiles(0);
    __syncthreads();
    int cur = 0;
    const int NIT = KTOT / 8;  /* 288 */
    for (int it = 0; it < NIT; it++) {
        if (it + 1 < NIT) loadTiles(it + 1);
#pragma unroll
        for (int kk = 0; kk < 8; kk++) {
            float4 a0 = *reinterpret_cast<const float4*>(&As[cur][kk][ty * 8]);
            float4 a1 = *reinterpret_cast<const float4*>(&As[cur][kk][ty * 8 + 4]);
            ulonglong2 bb0 = *reinterpret_cast<const ulonglong2*>(&Bs[cur][kk][tx * 4]);
            ulonglong2 bb1 = *reinterpret_cast<const ulonglong2*>(&Bs[cur][kk][64 + tx * 4]);
            unsigned long long b2[4] = {bb0.x, bb0.y, bb1.x, bb1.y};
            float av[8] = {a0.x, a0.y, a0.z, a0.w, a1.x, a1.y, a1.z, a1.w};
            unsigned long long a2[8];
#pragma unroll
            for (int i = 0; i < 8; i++) {
                unsigned ai = __float_as_uint(av[i]);
                asm("mov.b64 %0, {%1, %1};" : "=l"(a2[i]) : "r"(ai));
            }
#pragma unroll
            for (int i = 0; i < 8; i++)
#pragma unroll
                for (int j = 0; j < 4; j++)
                    asm("fma.rn.f32x2 %0, %1, %2, %3;"
                        : "=l"(acc2[i][j])
                        : "l"(a2[i]), "l"(b2[j]), "l"(acc2[i][j]));
        }
        if (it + 1 < NIT) {
            storeTiles(cur ^ 1);
            __syncthreads();
            cur ^= 1;
        }
    }
    /* epilogue: unpack pairs; columns p0+tx*4 (j 0-1) and p0+64+tx*4 (j 2-3) */
#pragma unroll
    for (int i = 0; i < 8; i++) {
        int m = m0 + ty * 8 + i;
        float bv = bias[m];
        float v[8];
#pragma unroll
        for (int j = 0; j < 4; j++) {
            unsigned lo, hi;
            asm("mov.b64 {%0, %1}, %2;" : "=r"(lo), "=r"(hi) : "l"(acc2[i][j]));
            v[j * 2 + 0] = __uint_as_float(lo);
            v[j * 2 + 1] = __uint_as_float(hi);
        }
        float4 o0, o1;
        o0.x = fmaxf(__fadd_rn(v[0], bv), 0.f);
        o0.y = fmaxf(__fadd_rn(v[1], bv), 0.f);
        o0.z = fmaxf(__fadd_rn(v[2], bv), 0.f);
        o0.w = fmaxf(__fadd_rn(v[3], bv), 0.f);
        o1.x = fmaxf(__fadd_rn(v[4], bv), 0.f);
        o1.y = fmaxf(__fadd_rn(v[5], bv), 0.f);
        o1.z = fmaxf(__fadd_rn(v[6], bv), 0.f);
        o1.w = fmaxf(__fadd_rn(v[7], bv), 0.f);
        int pA = p0 + tx * 4;
        int pB = p0 + 64 + tx * 4;
        if (pA < HWNUM) *reinterpret_cast<float4*>(&g_t[(size_t)m * HWNUM + pA]) = o0;
        if (pB < HWNUM) *reinterpret_cast<float4*>(&g_t[(size_t)m * HWNUM + pB]) = o1;
    }
}

/* --- 1x1 heads: 2 channel-groups x 2 pixels per thread ---------------------
   128 thr/block, 625 blocks -> 1250 warps AND 2-pixel ILP. Channel group 0 =
   ch 0..22, group 1 = ch 22..44 (ch 22 duplicated; identical sequential
   accumulation in both -> identical bits; it's a delta, duplicate store OK). */
__global__ __launch_bounds__(128)
void heads_kernel(const float* __restrict__ wObj, const float* __restrict__ bObj,
                  const float* __restrict__ wReg, const float* __restrict__ bReg) {
    __shared__ float ws[45 * 256];
    __shared__ float bs[45];
    int tid = threadIdx.x;   /* 128 threads */
    for (int i = tid; i < 9 * 256; i += 128) ws[i] = wObj[i];
    for (int i = tid; i < 36 * 256; i += 128) ws[9 * 256 + i] = wReg[i];
    if (tid < 9) bs[tid] = bObj[tid];
    if (tid < 36) bs[9 + tid] = bReg[tid];
    __syncthreads();

    int og = tid >> 6;                 /* 0 or 1: channel group          */
    int px = tid & 63;                 /* pixel slot                     */
    int start = og * 22;               /* ch 0..22 or 22..44             */
    int p0 = blockIdx.x * 128 + px;
    int p1 = p0 + 64;
    bool v0 = p0 < HWNUM, v1 = p1 < HWNUM;
    const float* wsg = ws + start * 256;
    float acc0[23], acc1[23];
#pragma unroll
    for (int o = 0; o < 23; o++) { acc0[o] = 0.f; acc1[o] = 0.f; }
#pragma unroll 4
    for (int ci = 0; ci < 256; ci++) {
        float a0 = v0 ? g_t[(size_t)ci * HWNUM + p0] : 0.f;
        float a1 = v1 ? g_t[(size_t)ci * HWNUM + p1] : 0.f;
#pragma unroll
        for (int o = 0; o < 23; o++) {
            float wv = wsg[o * 256 + ci];
            acc0[o] = fmaf(a0, wv, acc0[o]);
            acc1[o] = fmaf(a1, wv, acc1[o]);
        }
    }
#pragma unroll
    for (int oo = 0; oo < 23; oo++) {
        int o = start + oo;
        if (v0) {
            float s = __fadd_rn(acc0[oo], bs[o]);
            if (o < 9) {
                unsigned u = __float_as_uint(s);
                unsigned key = (u & 0x80000000u) ? ~u : (u | 0x80000000u);
                g_keys[p0 * 9 + o] = key;
                atomicAdd(&g_hist1[key >> 16], 1);
            } else {
                g_deltas[(size_t)p0 * 36 + (o - 9)] = s;
            }
        }
        if (v1) {
            float s = __fadd_rn(acc1[oo], bs[o]);
            if (o < 9) {
                unsigned u = __float_as_uint(s);
                unsigned key = (u & 0x80000000u) ? ~u : (u | 0x80000000u);
                g_keys[p1 * 9 + o] = key;
                atomicAdd(&g_hist1[key >> 16], 1);
            } else {
                g_deltas[(size_t)p1 * 36 + (o - 9)] = s;
            }
        }
    }
}

/* ------ segment sums: 1024 segments x 64 bins, int4 loads, 16 SMs ---------- */
__global__ void segsum_kernel() {
    int seg = blockIdx.x * 64 + threadIdx.x;   /* <<<16,64>>> : 0..1023 */
    int lo = 65536 - seg * 64 - 64;
    int s = 0;
#pragma unroll
    for (int k = 0; k < 16; k++) {
        int4 v = *reinterpret_cast<const int4*>(&g_hist1[lo + k * 4]);
        s += v.x + v.y + v.z + v.w;
    }
    g_seg[seg] = s;
}

/* ---- select: scan 1024 segsums, crossing thread walks its 64 bins --------- */
__global__ void select_kernel() {
    __shared__ int csum[1024];
    int t = threadIdx.x;
    int s = g_seg[t];
    csum[t] = s;
    __syncthreads();
    for (int off = 1; off < 1024; off <<= 1) {
        int v = (t >= off) ? csum[t - off] : 0;
        __syncthreads();
        csum[t] += v;
        __syncthreads();
    }
    int incl = csum[t];
    int excl = incl - s;
    if (excl < PRE && incl >= PRE) {
        int start = t * 64;
        int lo = 65536 - start - 64;
        int vals[64];
#pragma unroll
        for (int k4 = 0; k4 < 16; k4++) {
            int4 v = *reinterpret_cast<const int4*>(&g_hist1[lo + k4 * 4]);
            vals[k4 * 4 + 0] = v.x;
            vals[k4 * 4 + 1] = v.y;
            vals[k4 * 4 + 2] = v.z;
            vals[k4 * 4 + 3] = v.w;
        }
        int acc = excl;
#pragma unroll
        for (int k = 0; k < 64; k++) {
            int c = vals[63 - k];
            if (acc + c >= PRE) { g_selHigh = 65535 - (start + k); break; }
            acc += c;
        }
    }
}

/* ------- compact: all keys with high16 >= selHigh, as 64-bit composites ----- */
__global__ void compact_kernel() {
    int i = blockIdx.x * blockDim.x + threadIdx.x;
    if (i >= NSCORE) return;
    unsigned k = g_keys[i];
    if ((int)(k >> 16) >= g_selHigh) {
        int pos = atomicAdd(&g_cntHigh, 1);
        if (pos < 8192)
            g_list[pos] = (((unsigned long long)k) << 32) |
                          (unsigned long long)(0xFFFFFFFFu - (unsigned)i);
    }
}

/* descending bitonic sort of the 8192 composites (zeros sink to the end); the */
/* first PRE entries afterwards are exactly lax.top_k order (key desc,idx asc) */
__global__ void sort_kernel() {
    extern __shared__ unsigned long long sm[];
    int t = threadIdx.x;
    for (int i = t; i < 8192; i += 1024) sm[i] = g_list[i];
    __syncthreads();
    for (int k = 2; k <= 8192; k <<= 1)
        for (int j = k >> 1; j > 0; j >>= 1) {
            for (int i = t; i < 8192; i += 1024) {
                int l = i ^ j;
                if (l > i) {
                    unsigned long long a = sm[i], b = sm[l];
                    bool up = ((i & k) == 0);
                    if ((a < b) == up) { sm[i] = b; sm[l] = a; }
                }
            }
            __syncthreads();
        }
    for (int i = t; i < 8192; i += 1024) g_list[i] = sm[i];
}

/* ---------------- decode/clip — exact fp32, UNFUSED (match XLA) ------------ */
__global__ void decode_kernel(const float* __restrict__ anchors) {
    int j = blockIdx.x * blockDim.x + threadIdx.x;
    if (j >= PRE) return;
    unsigned long long comp = g_list[j];
    unsigned idx = 0xFFFFFFFFu - (unsigned)(comp & 0xFFFFFFFFull);
    float4 an = reinterpret_cast<const float4*>(anchors)[idx];
    float4 dl = reinterpret_cast<const float4*>(g_deltas)[idx];
    float wa = __fsub_rn(an.z, an.x);
    float ha = __fsub_rn(an.w, an.y);
    float xa = __fadd_rn(an.x, __fmul_rn(0.5f, wa));
    float ya = __fadd_rn(an.y, __fmul_rn(0.5f, ha));
    float dw = fminf(dl.z, BCLIP), dh = fminf(dl.w, BCLIP);
    float cx = __fadd_rn(__fmul_rn(dl.x, wa), xa);
    float cy = __fadd_rn(__fmul_rn(dl.y, ha), ya);
    float ew = (float)exp((double)dw);   /* exactly-rounded fp32 exp */
    float eh = (float)exp((double)dh);
    float wb = __fmul_rn(ew, wa);
    float hb = __fmul_rn(eh, ha);
    float x1 = __fsub_rn(cx, __fmul_rn(0.5f, wb));
    float y1 = __fsub_rn(cy, __fmul_rn(0.5f, hb));
    float x2 = __fadd_rn(cx, __fmul_rn(0.5f, wb));
    float y2 = __fadd_rn(cy, __fmul_rn(0.5f, hb));
    x1 = fminf(fmaxf(x1, 0.f), IMGSZ);
    y1 = fminf(fmaxf(y1, 0.f), IMGSZ);
    x2 = fminf(fmaxf(x2, 0.f), IMGSZ);
    y2 = fminf(fmaxf(y2, 0.f), IMGSZ);
    reinterpret_cast<float4*>(g_boxes)[j] = make_float4(x1, y1, x2, y2);
    g_valid[j] = (__fsub_rn(x2, x1) >= MINSZ) && (__fsub_rn(y2, y1) >= MINSZ);
}

/* ----------- NMS suppression mask — exact fp32, UNFUSED (match XLA) -------- */
__global__ void nms_mask_kernel() {
    int rb = blockIdx.y, cb = blockIdx.x;
    if (cb < rb) return;
    int t = threadIdx.x;
    __shared__ float4 cbox[64];
    int j0 = cb * 64;
    int jg = j0 + t;
    cbox[t] = (jg < PRE) ? reinterpret_cast<const float4*>(g_boxes)[jg]
                         : make_float4(0.f, 0.f, 0.f, 0.f);
    __syncthreads();
    int i = rb * 64 + t;
    if (i >= PRE) return;
    unsigned long long bits = 0ull;
    if (j0 + 63 > i) {
        float4 b = reinterpret_cast<const float4*>(g_boxes)[i];
        float a1 = __fmul_rn(__fsub_rn(b.z, b.x), __fsub_rn(b.w, b.y));
        int jmax = min(64, PRE - j0);
        for (int jj = 0; jj < jmax; jj++) {
            int j = j0 + jj;
            if (j <= i) continue;
            float4 c = cbox[jj];
            float lx = fmaxf(b.x, c.x), ly = fmaxf(b.y, c.y);
            float rx = fminf(b.z, c.z), ry = fminf(b.w, c.w);
            float iw = fmaxf(__fsub_rn(rx, lx), 0.f);
            float ih = fmaxf(__fsub_rn(ry, ly), 0.f);
            float inter = __fmul_rn(iw, ih);
            float a2 = __fmul_rn(__fsub_rn(c.z, c.x), __fsub_rn(c.w, c.y));
            float den = fmaxf(__fsub_rn(__fadd_rn(a1, a2), inter), 1e-6f);
            float iou = __fdiv_rn(inter, den);
            if (iou > NMS_THR) bits |= (1ull << jj);
        }
    }
    g_mask[(size_t)i * MASKW + cb] = bits;
}

/* -- greedy scan: double-buffered prefetch, smem-only critical chain, -------
   deferred parallel output of kept boxes                                     */
#define CHUNK 64
__global__ void nms_scan_kernel(float* __restrict__ out) {
    extern __shared__ unsigned long long sm2[];
    unsigned long long* bufA = sm2;                       /* CHUNK*MASKW      */
    unsigned long long* bufB = sm2 + CHUNK * MASKW;       /* CHUNK*MASKW      */
    volatile unsigned long long* rem = sm2 + 2 * CHUNK * MASKW;   /* MASKW    */
    int* kept = (int*)(sm2 + 2 * CHUNK * MASKW + MASKW);  /* POST ints        */
    __shared__ int s_nkept;
    int tid = threadIdx.x;   /* 256 threads */

    for (int i = tid; i < POST * 4; i += 256) out[i] = 0.f;
    for (int w = tid; w < MASKW; w += 256) {
        unsigned long long m = 0ull;
        int base = w * 64;
        for (int k = 0; k < 64; k++) {
            int j = base + k;
            if (j >= PRE || !g_valid[j]) m |= (1ull << k);
        }
        rem[w] = m;
    }
    if (tid == 0) s_nkept = 0;
    /* prefetch chunk 0 into bufA (all threads) */
    for (int idx = tid; idx < CHUNK * MASKW; idx += 256) {
        int rr = idx / MASKW, col = idx - rr * MASKW;
        bufA[idx] = (rr < PRE) ? g_mask[(size_t)rr * MASKW + col] : 0ull;
    }
    __syncthreads();

    for (int c = 0; c < MASKW; c++) {
        unsigned long long* curb = (c & 1) ? bufB : bufA;
        unsigned long long* nxtb = (c & 1) ? bufA : bufB;
        if (tid >= 32) {
            /* warps 1-7: prefetch chunk c+1 (only words >= c+1 are ever read) */
            if (c + 1 < MASKW) {
                int base_i = (c + 1) * CHUNK;
                for (int idx = tid - 32; idx < CHUNK * MASKW; idx += 224) {
                    int rr = idx / MASKW, col = idx - rr * MASKW;
                    int gi = base_i + rr;
                    nxtb[idx] = (gi < PRE && col > c) ? g_mask[(size_t)gi * MASKW + col] : 0ull;
                }
            }
        } else {
            int lane = tid;
            int nk = s_nkept;
            int base_i = c * CHUNK;
            for (int bit = 0; bit < CHUNK; bit++) {
                int i = base_i + bit;
                if (i >= PRE || nk >= POST) break;
                if (!((rem[c] >> bit) & 1ull)) {
                    if (lane == 0) kept[nk] = i;
                    nk++;
                    const unsigned long long* row = &curb[bit * MASKW];
                    for (int w = c + lane; w < MASKW; w += 32)
                        rem[w] = rem[w] | row[w];
                    __syncwarp();
                }
            }
            if (lane == 0) s_nkept = nk;
        }
        __syncthreads();
        if (s_nkept >= POST) break;
    }
    __syncthreads();
    /* parallel output of kept boxes (no latency in the critical chain) */
    int nk = s_nkept;
    for (int idx = tid; idx < nk * 4; idx += 256) {
        int k = idx >> 2, j = idx & 3;
        out[idx] = g_boxes[kept[k] * 4 + j];
    }
}

/* --------------------------------- launch ---------------------------------- */
extern "C" void kernel_launch(void* const* d_in, const int* in_sizes, int n_in,
                              void* d_out, int out_size) {
    (void)in_sizes; (void)n_in; (void)out_size;
    const float* feature = (const float*)d_in[0];
    const float* anchors = (const float*)d_in[1];
    const float* w_conv  = (const float*)d_in[2];
    const float* b_conv  = (const float*)d_in[3];
    const float* w_obj   = (const float*)d_in[4];
    const float* b_obj   = (const float*)d_in[5];
    const float* w_reg   = (const float*)d_in[6];
    const float* b_reg   = (const float*)d_in[7];
    float* out = (float*)d_out;

    const int scan_smem = (2 * CHUNK * MASKW + MASKW) * 8 + POST * 4;
    cudaFuncSetAttribute(sort_kernel, cudaFuncAttributeMaxDynamicSharedMemorySize, 65536);
    cudaFuncSetAttribute(nms_scan_kernel, cudaFuncAttributeMaxDynamicSharedMemorySize, scan_smem);

    zero_kernel<<<256, 256>>>();
    transpose_w_kernel<<<(KTOT * 256 + 255) / 256, 256>>>(w_conv);
    conv3x3_kernel<<<dim3(313, 2), 256>>>(feature, b_conv);
    heads_kernel<<<313, 128>>>(w_obj, b_obj, w_reg, b_reg);
    segsum_kernel<<<16, 64>>>();
    select_kernel<<<1, 1024>>>();
    compact_kernel<<<1407, 256>>>();
    sort_kernel<<<1, 1024, 65536>>>();
    decode_kernel<<<24, 256>>>(anchors);
    nms_mask_kernel<<<dim3(94, 94), 64>>>();
    nms_scan_kernel<<<1, 256, scan_smem>>>(out);
}

// round 16
// speedup vs baseline: 1.2560x; 1.0270x over previous
#include <cuda_runtime.h>
#include <math.h>
#include <stdint.h>

#define C_IN   256
#define HGT    200
#define WID    200
#define HWNUM  40000
#define NA     9
#define KTOT   2304
#define NSCORE 360000
#define PRE    6000
#define POST   1000
#define IMGSZ  1600.0f
#define NMS_THR 0.7f
#define MINSZ  1.0f
#define BCLIP  4.135166556742356f   /* log(1000/16) */
#define MASKW  94                   /* ceil(6000/64) */
#define WS_PITCH 260                /* 45-row weight pitch, bank-spreads o */

/* ------------------------- scratch (device globals) ------------------------ */
__device__ float              g_wT[KTOT * 256];           /* w transposed: [k'][m] */
__device__ float              g_t[C_IN * HWNUM];          /* conv output (relu'd) */
__device__ unsigned int       g_keys[NSCORE];             /* monotone score keys  */
__device__ float              g_deltas[NSCORE * 4];
__device__ int                g_hist1[65536];
__device__ int                g_seg[1024];
__device__ int                g_selHigh;
__device__ int                g_cntHigh;
__device__ unsigned long long g_list[8192];               /* (key<<32)|(~idx)     */
__device__ float              g_boxes[PRE * 4];
__device__ int                g_valid[PRE];
__device__ unsigned long long g_mask[(size_t)PRE * MASKW];

/* --------------------------------- zero ----------------------------------- */
__global__ void zero_kernel() {
    int i = blockIdx.x * blockDim.x + threadIdx.x;
    if (i < 65536) g_hist1[i] = 0;
    if (i < 8192)  g_list[i] = 0ull;
    if (i == 0)    g_cntHigh = 0;
}

/* ------------- one-time weight transpose: wT[k'][m], k'=(rs,ci) ------------ */
__global__ void transpose_w_kernel(const float* __restrict__ w) {
    int idx = blockIdx.x * blockDim.x + threadIdx.x;   /* write-coalesced in m */
    if (idx >= KTOT * 256) return;
    int kp = idx >> 8;          /* k' = rs*256 + ci */
    int m  = idx & 255;
    int ci = kp & 255;
    int rs = kp >> 8;
    g_wT[idx] = w[(size_t)m * KTOT + ci * 9 + rs];
}

/* ---- 3x3 conv (implicit GEMM, sequential FMA over k' = (r,s,ci) order) ---- */
/* Bit-exact anchor preserved: each output element accumulates k'=0..2303      */
/* strictly in order (f32x2 halves round RN identically to scalar FFMA).       */
__global__ __launch_bounds__(256, 2)
void conv3x3_kernel(const float* __restrict__ x, const float* __restrict__ bias) {
    __shared__ __align__(16) float As[2][8][128];
    __shared__ __align__(16) float Bs[2][8][128];
    const int tid = threadIdx.x;
    const int m0 = blockIdx.y * 128;
    const int p0 = blockIdx.x * 128;
    const int kr = tid >> 5;           /* 0..7   : k-row within tile   */
    const int lc = (tid & 31) * 4;     /* 0..124 : column (m or p)     */
    const int tx = tid & 15, ty = tid >> 4;

    float4 aReg = make_float4(0.f, 0.f, 0.f, 0.f);
    float4 bReg = make_float4(0.f, 0.f, 0.f, 0.f);

    auto loadTiles = [&](int it) {
        int k0 = it * 8;
        aReg = *reinterpret_cast<const float4*>(&g_wT[(size_t)(k0 + kr) * 256 + m0 + lc]);
        int kp = k0 + kr;
        int rs = kp >> 8;
        int ci = kp & 255;
        int r = rs / 3 - 1;
        int s = rs - (rs / 3) * 3 - 1;
        const float* base = x + (size_t)ci * HWNUM;
        float bv[4];
#pragma unroll
        for (int jj = 0; jj < 4; jj++) {
            int p = p0 + lc + jj;
            float v = 0.f;
            if (p < HWNUM) {
                int h = p / 200;
                int wc = p - h * 200;
                int hh = h + r, wcc = wc + s;
                if (hh >= 0 && hh < HGT && wcc >= 0 && wcc < WID)
                    v = base[hh * WID + wcc];
            }
            bv[jj] = v;
        }
        bReg = make_float4(bv[0], bv[1], bv[2], bv[3]);
    };
    auto storeTiles = [&](int buf) {
        *reinterpret_cast<float4*>(&As[buf][kr][lc]) = aReg;
        *reinterpret_cast<float4*>(&Bs[buf][kr][lc]) = bReg;
    };

    unsigned long long acc2[8][4];
#pragma unroll
    for (int i = 0; i < 8; i++)
#pragma unroll
        for (int j = 0; j < 4; j++) acc2[i][j] = 0ull;

    loadTiles(0);
    storeTiles(0);
    __syncthreads();
    int cur = 0;
    const int NIT = KTOT / 8;  /* 288 */
    for (int it = 0; it < NIT; it++) {
        if (it + 1 < NIT) loadTiles(it + 1);
#pragma unroll
        for (int kk = 0; kk < 8; kk++) {
            float4 a0 = *reinterpret_cast<const float4*>(&As[cur][kk][ty * 8]);
            float4 a1 = *reinterpret_cast<const float4*>(&As[cur][kk][ty * 8 + 4]);
            ulonglong2 bb0 = *reinterpret_cast<const ulonglong2*>(&Bs[cur][kk][tx * 4]);
            ulonglong2 bb1 = *reinterpret_cast<const ulonglong2*>(&Bs[cur][kk][64 + tx * 4]);
            unsigned long long b2[4] = {bb0.x, bb0.y, bb1.x, bb1.y};
            float av[8] = {a0.x, a0.y, a0.z, a0.w, a1.x, a1.y, a1.z, a1.w};
            unsigned long long a2[8];
#pragma unroll
            for (int i = 0; i < 8; i++) {
                unsigned ai = __float_as_uint(av[i]);
                asm("mov.b64 %0, {%1, %1};" : "=l"(a2[i]) : "r"(ai));
            }
#pragma unroll
            for (int i = 0; i < 8; i++)
#pragma unroll
                for (int j = 0; j < 4; j++)
                    asm("fma.rn.f32x2 %0, %1, %2, %3;"
                        : "=l"(acc2[i][j])
                        : "l"(a2[i]), "l"(b2[j]), "l"(acc2[i][j]));
        }
        if (it + 1 < NIT) {
            storeTiles(cur ^ 1);
            __syncthreads();
            cur ^= 1;
        }
    }
    /* epilogue: unpack pairs; columns p0+tx*4 (j 0-1) and p0+64+tx*4 (j 2-3) */
#pragma unroll
    for (int i = 0; i < 8; i++) {
        int m = m0 + ty * 8 + i;
        float bv = bias[m];
        float v[8];
#pragma unroll
        for (int j = 0; j < 4; j++) {
            unsigned lo, hi;
            asm("mov.b64 {%0, %1}, %2;" : "=r"(lo), "=r"(hi) : "l"(acc2[i][j]));
            v[j * 2 + 0] = __uint_as_float(lo);
            v[j * 2 + 1] = __uint_as_float(hi);
        }
        float4 o0, o1;
        o0.x = fmaxf(__fadd_rn(v[0], bv), 0.f);
        o0.y = fmaxf(__fadd_rn(v[1], bv), 0.f);
        o0.z = fmaxf(__fadd_rn(v[2], bv), 0.f);
        o0.w = fmaxf(__fadd_rn(v[3], bv), 0.f);
        o1.x = fmaxf(__fadd_rn(v[4], bv), 0.f);
        o1.y = fmaxf(__fadd_rn(v[5], bv), 0.f);
        o1.z = fmaxf(__fadd_rn(v[6], bv), 0.f);
        o1.w = fmaxf(__fadd_rn(v[7], bv), 0.f);
        int pA = p0 + tx * 4;
        int pB = p0 + 64 + tx * 4;
        if (pA < HWNUM) *reinterpret_cast<float4*>(&g_t[(size_t)m * HWNUM + pA]) = o0;
        if (pB < HWNUM) *reinterpret_cast<float4*>(&g_t[(size_t)m * HWNUM + pB]) = o1;
    }
}

/* --- 1x1 heads as tiled GEMM: M=48(ch) x N=128(px)/block, K=256 ------------
   Thread tile 6ch x 8px -> 48 FMA per 8 LDS. Each output channel keeps ONE
   accumulator stepped ci=0..255 ascending -> bit-exact.                      */
__global__ __launch_bounds__(128)
void heads_kernel(const float* __restrict__ wObj, const float* __restrict__ bObj,
                  const float* __restrict__ wReg, const float* __restrict__ bReg) {
    extern __shared__ float hs[];
    float* wsp = hs;                          /* 48 x WS_PITCH               */
    float* bsp = hs + 48 * WS_PITCH;          /* 48                          */
    float* Bsh = bsp + 48;                    /* 32 x 128                    */
    int tid = threadIdx.x;   /* 128 threads */

    for (int i = tid; i < 9 * 256; i += 128)
        wsp[(i >> 8) * WS_PITCH + (i & 255)] = wObj[i];
    for (int i = tid; i < 36 * 256; i += 128)
        wsp[(9 + (i >> 8)) * WS_PITCH + (i & 255)] = wReg[i];
    for (int i = tid; i < 3 * WS_PITCH; i += 128)
        wsp[45 * WS_PITCH + i] = 0.f;
    if (tid < 9) bsp[tid] = bObj[tid];
    else if (tid < 45) bsp[tid] = bReg[tid - 9];
    else if (tid < 48) bsp[tid] = 0.f;

    int tx = tid & 15, ty = tid >> 4;         /* tx: px group, ty: ch group  */
    int p0 = blockIdx.x * 128;
    bool full = (p0 + 128 <= HWNUM);

    float acc[6][8];
#pragma unroll
    for (int oo = 0; oo < 6; oo++)
#pragma unroll
        for (int jj = 0; jj < 8; jj++) acc[oo][jj] = 0.f;

    for (int kt = 0; kt < 8; kt++) {
        int k0 = kt * 32;
        __syncthreads();
        /* stage B tile: g_t[k0..k0+31][p0..p0+127] -> Bsh[kk][px] */
        if (full) {
#pragma unroll
            for (int q = 0; q < 8; q++) {
                int idx = tid + 128 * q;      /* float4 index 0..1023 */
                int kk = idx >> 5;
                int px = (idx & 31) * 4;
                float4 v = *reinterpret_cast<const float4*>(
                    &g_t[(size_t)(k0 + kk) * HWNUM + p0 + px]);
                *reinterpret_cast<float4*>(&Bsh[kk * 128 + px]) = v;
            }
        } else {
#pragma unroll
            for (int q = 0; q < 8; q++) {
                int idx = tid + 128 * q;
                int kk = idx >> 5;
                int px = (idx & 31) * 4;
#pragma unroll
                for (int e = 0; e < 4; e++) {
                    int p = p0 + px + e;
                    Bsh[kk * 128 + px + e] =
                        (p < HWNUM) ? g_t[(size_t)(k0 + kk) * HWNUM + p] : 0.f;
                }
            }
        }
        __syncthreads();
#pragma unroll 4
        for (int kk = 0; kk < 32; kk++) {
            float4 b0 = *reinterpret_cast<const float4*>(&Bsh[kk * 128 + tx * 4]);
            float4 b1 = *reinterpret_cast<const float4*>(&Bsh[kk * 128 + 64 + tx * 4]);
            float bvv[8] = {b0.x, b0.y, b0.z, b0.w, b1.x, b1.y, b1.z, b1.w};
            float wv[6];
#pragma unroll
            for (int oo = 0; oo < 6; oo++)
                wv[oo] = wsp[(ty * 6 + oo) * WS_PITCH + k0 + kk];
#pragma unroll
            for (int oo = 0; oo < 6; oo++)
#pragma unroll
                for (int jj = 0; jj < 8; jj++)
                    acc[oo][jj] = fmaf(wv[oo], bvv[jj], acc[oo][jj]);
        }
    }

    /* epilogue */
#pragma unroll
    for (int oo = 0; oo < 6; oo++) {
        int o = ty * 6 + oo;
        if (o >= 45) continue;
        float bv = bsp[o];
#pragma unroll
        for (int jj = 0; jj < 8; jj++) {
            int p = (jj < 4) ? (p0 + tx * 4 + jj) : (p0 + 64 + tx * 4 + (jj - 4));
            if (p >= HWNUM) continue;
            float s = __fadd_rn(acc[oo][jj], bv);
            if (o < 9) {
                unsigned u = __float_as_uint(s);
                unsigned key = (u & 0x80000000u) ? ~u : (u | 0x80000000u);
                g_keys[p * 9 + o] = key;
                atomicAdd(&g_hist1[key >> 16], 1);
            } else {
                g_deltas[(size_t)p * 36 + (o - 9)] = s;
            }
        }
    }
}

/* ------ segment sums: 1024 segments x 64 bins, int4 loads, 16 SMs ---------- */
__global__ void segsum_kernel() {
    int seg = blockIdx.x * 64 + threadIdx.x;   /* <<<16,64>>> : 0..1023 */
    int lo = 65536 - seg * 64 - 64;
    int s = 0;
#pragma unroll
    for (int k = 0; k < 16; k++) {
        int4 v = *reinterpret_cast<const int4*>(&g_hist1[lo + k * 4]);
        s += v.x + v.y + v.z + v.w;
    }
    g_seg[seg] = s;
}

/* ---- select: scan 1024 segsums, crossing thread walks its 64 bins --------- */
__global__ void select_kernel() {
    __shared__ int csum[1024];
    int t = threadIdx.x;
    int s = g_seg[t];
    csum[t] = s;
    __syncthreads();
    for (int off = 1; off < 1024; off <<= 1) {
        int v = (t >= off) ? csum[t - off] : 0;
        __syncthreads();
        csum[t] += v;
        __syncthreads();
    }
    int incl = csum[t];
    int excl = incl - s;
    if (excl < PRE && incl >= PRE) {
        int start = t * 64;
        int lo = 65536 - start - 64;
        int vals[64];
#pragma unroll
        for (int k4 = 0; k4 < 16; k4++) {
            int4 v = *reinterpret_cast<const int4*>(&g_hist1[lo + k4 * 4]);
            vals[k4 * 4 + 0] = v.x;
            vals[k4 * 4 + 1] = v.y;
            vals[k4 * 4 + 2] = v.z;
            vals[k4 * 4 + 3] = v.w;
        }
        int acc = excl;
#pragma unroll
        for (int k = 0; k < 64; k++) {
            int c = vals[63 - k];
            if (acc + c >= PRE) { g_selHigh = 65535 - (start + k); break; }
            acc += c;
        }
    }
}

/* ------- compact: all keys with high16 >= selHigh, as 64-bit composites ----- */
__global__ void compact_kernel() {
    int i = blockIdx.x * blockDim.x + threadIdx.x;
    if (i >= NSCORE) return;
    unsigned k = g_keys[i];
    if ((int)(k >> 16) >= g_selHigh) {
        int pos = atomicAdd(&g_cntHigh, 1);
        if (pos < 8192)
            g_list[pos] = (((unsigned long long)k) << 32) |
                          (unsigned long long)(0xFFFFFFFFu - (unsigned)i);
    }
}

/* descending bitonic sort of the 8192 composites (zeros sink to the end); the */
/* first PRE entries afterwards are exactly lax.top_k order (key desc,idx asc) */
__global__ void sort_kernel() {
    extern __shared__ unsigned long long sm[];
    int t = threadIdx.x;
    for (int i = t; i < 8192; i += 1024) sm[i] = g_list[i];
    __syncthreads();
    for (int k = 2; k <= 8192; k <<= 1)
        for (int j = k >> 1; j > 0; j >>= 1) {
            for (int i = t; i < 8192; i += 1024) {
                int l = i ^ j;
                if (l > i) {
                    unsigned long long a = sm[i], b = sm[l];
                    bool up = ((i & k) == 0);
                    if ((a < b) == up) { sm[i] = b; sm[l] = a; }
                }
            }
            __syncthreads();
        }
    for (int i = t; i < 8192; i += 1024) g_list[i] = sm[i];
}

/* ---------------- decode/clip — exact fp32, UNFUSED (match XLA) ------------ */
__global__ void decode_kernel(const float* __restrict__ anchors) {
    int j = blockIdx.x * blockDim.x + threadIdx.x;
    if (j >= PRE) return;
    unsigned long long comp = g_list[j];
    unsigned idx = 0xFFFFFFFFu - (unsigned)(comp & 0xFFFFFFFFull);
    float4 an = reinterpret_cast<const float4*>(anchors)[idx];
    float4 dl = reinterpret_cast<const float4*>(g_deltas)[idx];
    float wa = __fsub_rn(an.z, an.x);
    float ha = __fsub_rn(an.w, an.y);
    float xa = __fadd_rn(an.x, __fmul_rn(0.5f, wa));
    float ya = __fadd_rn(an.y, __fmul_rn(0.5f, ha));
    float dw = fminf(dl.z, BCLIP), dh = fminf(dl.w, BCLIP);
    float cx = __fadd_rn(__fmul_rn(dl.x, wa), xa);
    float cy = __fadd_rn(__fmul_rn(dl.y, ha), ya);
    float ew = (float)exp((double)dw);   /* exactly-rounded fp32 exp */
    float eh = (float)exp((double)dh);
    float wb = __fmul_rn(ew, wa);
    float hb = __fmul_rn(eh, ha);
    float x1 = __fsub_rn(cx, __fmul_rn(0.5f, wb));
    float y1 = __fsub_rn(cy, __fmul_rn(0.5f, hb));
    float x2 = __fadd_rn(cx, __fmul_rn(0.5f, wb));
    float y2 = __fadd_rn(cy, __fmul_rn(0.5f, hb));
    x1 = fminf(fmaxf(x1, 0.f), IMGSZ);
    y1 = fminf(fmaxf(y1, 0.f), IMGSZ);
    x2 = fminf(fmaxf(x2, 0.f), IMGSZ);
    y2 = fminf(fmaxf(y2, 0.f), IMGSZ);
    reinterpret_cast<float4*>(g_boxes)[j] = make_float4(x1, y1, x2, y2);
    g_valid[j] = (__fsub_rn(x2, x1) >= MINSZ) && (__fsub_rn(y2, y1) >= MINSZ);
}

/* ----------- NMS suppression mask — exact fp32, UNFUSED (match XLA) -------- */
__global__ void nms_mask_kernel() {
    int rb = blockIdx.y, cb = blockIdx.x;
    if (cb < rb) return;
    int t = threadIdx.x;
    __shared__ float4 cbox[64];
    int j0 = cb * 64;
    int jg = j0 + t;
    cbox[t] = (jg < PRE) ? reinterpret_cast<const float4*>(g_boxes)[jg]
                         : make_float4(0.f, 0.f, 0.f, 0.f);
    __syncthreads();
    int i = rb * 64 + t;
    if (i >= PRE) return;
    unsigned long long bits = 0ull;
    if (j0 + 63 > i) {
        float4 b = reinterpret_cast<const float4*>(g_boxes)[i];
        float a1 = __fmul_rn(__fsub_rn(b.z, b.x), __fsub_rn(b.w, b.y));
        int jmax = min(64, PRE - j0);
        for (int jj = 0; jj < jmax; jj++) {
            int j = j0 + jj;
            if (j <= i) continue;
            float4 c = cbox[jj];
            float lx = fmaxf(b.x, c.x), ly = fmaxf(b.y, c.y);
            float rx = fminf(b.z, c.z), ry = fminf(b.w, c.w);
            float iw = fmaxf(__fsub_rn(rx, lx), 0.f);
            float ih = fmaxf(__fsub_rn(ry, ly), 0.f);
            float inter = __fmul_rn(iw, ih);
            float a2 = __fmul_rn(__fsub_rn(c.z, c.x), __fsub_rn(c.w, c.y));
            float den = fmaxf(__fsub_rn(__fadd_rn(a1, a2), inter), 1e-6f);
            float iou = __fdiv_rn(inter, den);
            if (iou > NMS_THR) bits |= (1ull << jj);
        }
    }
    g_mask[(size_t)i * MASKW + cb] = bits;
}

/* -- greedy scan: double-buffered prefetch, smem-only critical chain, -------
   deferred parallel output of kept boxes                                     */
#define CHUNK 64
__global__ void nms_scan_kernel(float* __restrict__ out) {
    extern __shared__ unsigned long long sm2[];
    unsigned long long* bufA = sm2;                       /* CHUNK*MASKW      */
    unsigned long long* bufB = sm2 + CHUNK * MASKW;       /* CHUNK*MASKW      */
    volatile unsigned long long* rem = sm2 + 2 * CHUNK * MASKW;   /* MASKW    */
    int* kept = (int*)(sm2 + 2 * CHUNK * MASKW + MASKW);  /* POST ints        */
    __shared__ int s_nkept;
    int tid = threadIdx.x;   /* 256 threads */

    for (int i = tid; i < POST * 4; i += 256) out[i] = 0.f;
    for (int w = tid; w < MASKW; w += 256) {
        unsigned long long m = 0ull;
        int base = w * 64;
        for (int k = 0; k < 64; k++) {
            int j = base + k;
            if (j >= PRE || !g_valid[j]) m |= (1ull << k);
        }
        rem[w] = m;
    }
    if (tid == 0) s_nkept = 0;
    /* prefetch chunk 0 into bufA (all threads) */
    for (int idx = tid; idx < CHUNK * MASKW; idx += 256) {
        int rr = idx / MASKW, col = idx - rr * MASKW;
        bufA[idx] = (rr < PRE) ? g_mask[(size_t)rr * MASKW + col] : 0ull;
    }
    __syncthreads();

    for (int c = 0; c < MASKW; c++) {
        unsigned long long* curb = (c & 1) ? bufB : bufA;
        unsigned long long* nxtb = (c & 1) ? bufA : bufB;
        if (tid >= 32) {
            /* warps 1-7: prefetch chunk c+1 (only words >= c+1 are ever read) */
            if (c + 1 < MASKW) {
                int base_i = (c + 1) * CHUNK;
                for (int idx = tid - 32; idx < CHUNK * MASKW; idx += 224) {
                    int rr = idx / MASKW, col = idx - rr * MASKW;
                    int gi = base_i + rr;
                    nxtb[idx] = (gi < PRE && col > c) ? g_mask[(size_t)gi * MASKW + col] : 0ull;
                }
            }
        } else {
            int lane = tid;
            int nk = s_nkept;
            int base_i = c * CHUNK;
            for (int bit = 0; bit < CHUNK; bit++) {
                int i = base_i + bit;
                if (i >= PRE || nk >= POST) break;
                if (!((rem[c] >> bit) & 1ull)) {
                    if (lane == 0) kept[nk] = i;
                    nk++;
                    const unsigned long long* row = &curb[bit * MASKW];
                    for (int w = c + lane; w < MASKW; w += 32)
                        rem[w] = rem[w] | row[w];
                    __syncwarp();
                }
            }
            if (lane == 0) s_nkept = nk;
        }
        __syncthreads();
        if (s_nkept >= POST) break;
    }
    __syncthreads();
    /* parallel output of kept boxes (no latency in the critical chain) */
    int nk = s_nkept;
    for (int idx = tid; idx < nk * 4; idx += 256) {
        int k = idx >> 2, j = idx & 3;
        out[idx] = g_boxes[kept[k] * 4 + j];
    }
}

/* --------------------------------- launch ---------------------------------- */
extern "C" void kernel_launch(void* const* d_in, const int* in_sizes, int n_in,
                              void* d_out, int out_size) {
    (void)in_sizes; (void)n_in; (void)out_size;
    const float* feature = (const float*)d_in[0];
    const float* anchors = (const float*)d_in[1];
    const float* w_conv  = (const float*)d_in[2];
    const float* b_conv  = (const float*)d_in[3];
    const float* w_obj   = (const float*)d_in[4];
    const float* b_obj   = (const float*)d_in[5];
    const float* w_reg   = (const float*)d_in[6];
    const float* b_reg   = (const float*)d_in[7];
    float* out = (float*)d_out;

    const int scan_smem = (2 * CHUNK * MASKW + MASKW) * 8 + POST * 4;
    const int heads_smem = (48 * WS_PITCH + 48 + 32 * 128) * 4;
    cudaFuncSetAttribute(sort_kernel, cudaFuncAttributeMaxDynamicSharedMemorySize, 65536);
    cudaFuncSetAttribute(nms_scan_kernel, cudaFuncAttributeMaxDynamicSharedMemorySize, scan_smem);
    cudaFuncSetAttribute(heads_kernel, cudaFuncAttributeMaxDynamicSharedMemorySize, heads_smem);

    zero_kernel<<<256, 256>>>();
    transpose_w_kernel<<<(KTOT * 256 + 255) / 256, 256>>>(w_conv);
    conv3x3_kernel<<<dim3(313, 2), 256>>>(feature, b_conv);
    heads_kernel<<<313, 128, heads_smem>>>(w_obj, b_obj, w_reg, b_reg);
    segsum_kernel<<<16, 64>>>();
    select_kernel<<<1, 1024>>>();
    compact_kernel<<<1407, 256>>>();
    sort_kernel<<<1, 1024, 65536>>>();
    decode_kernel<<<24, 256>>>(anchors);
    nms_mask_kernel<<<dim3(94, 94), 64>>>();
    nms_scan_kernel<<<1, 256, scan_smem>>>(out);
}